// round 15
// baseline (speedup 1.0000x reference)
#include <cuda_runtime.h>
#include <cuda_bf16.h>
#include <math.h>
#include <stdint.h>

// Problem constants
#define BATCH_ 32
#define RESO_ 56
#define L_ (RESO_ * RESO_)          // 3136
#define C_ 128
#define M_ (BATCH_ * L_)            // 100352 rows
#define HID_ 512
#define TOK_ 112                    // window tokens (56*2)
#define NWIN_ 28                    // windows per batch per branch

// Scratch buffers (device globals: allocation-free)
__device__ __nv_bfloat16 g_ln  [(size_t)M_ * C_];
__device__ __nv_bfloat16 g_qkv [(size_t)M_ * 3 * C_];
__device__ __nv_bfloat16 g_attn[(size_t)M_ * C_];
__device__ float         g_x   [(size_t)M_ * C_];
__device__ __nv_bfloat16 g_w   [196608];   // transposed bf16 weights

// ---------------------------------------------------------------------------
// PTX helpers (baseline PTX, portable to compute_103)
// ---------------------------------------------------------------------------
__device__ __forceinline__ uint32_t smem_u32(const void* p) {
    uint32_t a;
    asm("{ .reg .u64 t; cvta.to.shared.u64 t, %1; cvt.u32.u64 %0, t; }" : "=r"(a) : "l"(p));
    return a;
}
__device__ __forceinline__ void cp16(uint32_t dst, const void* src) {
    asm volatile("cp.async.cg.shared.global [%0], [%1], 16;" :: "r"(dst), "l"(src));
}
#define CP_COMMIT() asm volatile("cp.async.commit_group;" ::: "memory")
#define CP_WAIT1()  asm volatile("cp.async.wait_group 1;" ::: "memory")
#define CP_WAIT0()  asm volatile("cp.async.wait_group 0;" ::: "memory")

__device__ __forceinline__ void ldsm_x4(uint32_t& r0, uint32_t& r1,
                                        uint32_t& r2, uint32_t& r3, uint32_t addr) {
    asm volatile("ldmatrix.sync.aligned.m8n8.x4.shared.b16 {%0,%1,%2,%3}, [%4];"
                 : "=r"(r0), "=r"(r1), "=r"(r2), "=r"(r3) : "r"(addr));
}
__device__ __forceinline__ void ldsm_x4_t(uint32_t& r0, uint32_t& r1,
                                          uint32_t& r2, uint32_t& r3, uint32_t addr) {
    asm volatile("ldmatrix.sync.aligned.m8n8.x4.trans.shared.b16 {%0,%1,%2,%3}, [%4];"
                 : "=r"(r0), "=r"(r1), "=r"(r2), "=r"(r3) : "r"(addr));
}
__device__ __forceinline__ void mma_bf16(float* c, const uint32_t* a,
                                         uint32_t b0, uint32_t b1) {
    asm volatile("mma.sync.aligned.m16n8k16.row.col.f32.bf16.bf16.f32 "
                 "{%0,%1,%2,%3}, {%4,%5,%6,%7}, {%8,%9}, {%0,%1,%2,%3};"
                 : "+f"(c[0]), "+f"(c[1]), "+f"(c[2]), "+f"(c[3])
                 : "r"(a[0]), "r"(a[1]), "r"(a[2]), "r"(a[3]), "r"(b0), "r"(b1));
}

// ---------------------------------------------------------------------------
// LayerNorm (one warp per row) + folded weight convert/transpose in blocks<768.
// ---------------------------------------------------------------------------
__global__ __launch_bounds__(256) void ln_conv_kernel(
    const float* __restrict__ in, const float* __restrict__ g,
    const float* __restrict__ b, __nv_bfloat16* __restrict__ out,
    const float* __restrict__ qkv_w, const float* __restrict__ proj_w,
    const float* __restrict__ fc1_w, const float* __restrict__ fc2_w,
    __nv_bfloat16* __restrict__ wout)
{
    if (blockIdx.x < 768) {
        int i = blockIdx.x * 256 + threadIdx.x;
        float v;
        if (i < 49152) {
            int n = i >> 7, k = i & 127;
            v = qkv_w[(size_t)k * 384 + n];
        } else if (i < 65536) {
            int j = i - 49152;    int n = j >> 7, k = j & 127;
            v = proj_w[(size_t)k * 128 + n];
        } else if (i < 131072) {
            int j = i - 65536;    int n = j >> 7, k = j & 127;
            v = fc1_w[(size_t)k * 512 + n];
        } else {
            int j = i - 131072;   int n = j >> 9, k = j & 511;
            v = fc2_w[(size_t)k * 128 + n];
        }
        wout[i] = __float2bfloat16(v);
    }

    int warp = (blockIdx.x * blockDim.x + threadIdx.x) >> 5;
    int lane = threadIdx.x & 31;
    if (warp >= M_) return;
    float4 v = ((const float4*)(in + (size_t)warp * C_))[lane];
    float s = v.x + v.y + v.z + v.w;
    #pragma unroll
    for (int o = 16; o; o >>= 1) s += __shfl_xor_sync(0xffffffffu, s, o);
    float mu = s * (1.0f / C_);
    float dx = v.x - mu, dy = v.y - mu, dz = v.z - mu, dw = v.w - mu;
    float q = dx*dx + dy*dy + dz*dz + dw*dw;
    #pragma unroll
    for (int o = 16; o; o >>= 1) q += __shfl_xor_sync(0xffffffffu, q, o);
    float rs = rsqrtf(q * (1.0f / C_) + 1e-5f);
    float4 gg = ((const float4*)g)[lane];
    float4 bb = ((const float4*)b)[lane];
    __nv_bfloat162 p0 = __floats2bfloat162_rn(dx * rs * gg.x + bb.x, dy * rs * gg.y + bb.y);
    __nv_bfloat162 p1 = __floats2bfloat162_rn(dz * rs * gg.z + bb.z, dw * rs * gg.w + bb.w);
    uint2 u;
    u.x = *reinterpret_cast<uint32_t*>(&p0);
    u.y = *reinterpret_cast<uint32_t*>(&p1);
    ((uint2*)(out + (size_t)warp * C_))[lane] = u;
}

// ---------------------------------------------------------------------------
// QKV GEMM (K=128), proj_ln-style one-shot tile: M-tile 64, 8 warps (2m x 4n).
// D[M,384] = A[M,128] @ Wt[384,128]^T, n-block = blockIdx.x (0..2).
// No mid-loop syncs; 52 KB smem -> 4 blocks/SM.
// ---------------------------------------------------------------------------
__global__ __launch_bounds__(256, 4) void qkv_gemm_kernel(
    const __nv_bfloat16* __restrict__ A, const __nv_bfloat16* __restrict__ Bt,
    __nv_bfloat16* __restrict__ D)
{
    __shared__ __align__(16) char smA[64 * 272];
    __shared__ __align__(16) char smB[128 * 272];

    int tid = threadIdx.x;
    int warp = tid >> 5;
    int lane = tid & 31;
    int wm = warp >> 2;            // 0..1
    int wn = warp & 3;             // 0..3
    int mBase = blockIdx.y * 64;
    int nBase = blockIdx.x * 128;

    uint32_t sA = smem_u32(smA);
    uint32_t sB = smem_u32(smB);

    // One-shot load in two committed k-halves (each 128 B/row).
    #pragma unroll
    for (int kh = 0; kh < 2; kh++) {
        #pragma unroll
        for (int it = 0; it < 2; it++) {   // A half: 512 cp16
            int idx = it * 256 + tid;
            int r = idx >> 3, c = idx & 7;
            cp16(sA + r * 272 + kh * 128 + c * 16,
                 A + (size_t)(mBase + r) * 128 + kh * 64 + c * 8);
        }
        #pragma unroll
        for (int it = 0; it < 4; it++) {   // B half: 1024 cp16
            int idx = it * 256 + tid;
            int r = idx >> 3, c = idx & 7;
            cp16(sB + r * 272 + kh * 128 + c * 16,
                 Bt + (size_t)(nBase + r) * 128 + kh * 64 + c * 8);
        }
        CP_COMMIT();
    }

    float acc[2][4][4];
    #pragma unroll
    for (int i = 0; i < 2; i++)
        #pragma unroll
        for (int j = 0; j < 4; j++)
            #pragma unroll
            for (int q = 0; q < 4; q++) acc[i][j][q] = 0.0f;

    #pragma unroll
    for (int kh = 0; kh < 2; kh++) {
        if (kh == 0) CP_WAIT1(); else CP_WAIT0();
        __syncthreads();
        #pragma unroll
        for (int ki = 0; ki < 4; ki++) {
            int ks = kh * 4 + ki;
            uint32_t af[2][4];
            #pragma unroll
            for (int mt = 0; mt < 2; mt++) {
                int row = wm * 32 + mt * 16 + (lane & 15);
                int koff = ks * 16 + ((lane >> 4) << 3);
                ldsm_x4(af[mt][0], af[mt][1], af[mt][2], af[mt][3],
                        sA + row * 272 + koff * 2);
            }
            uint32_t bf[2][4];
            #pragma unroll
            for (int nt2 = 0; nt2 < 2; nt2++) {
                int row = wn * 32 + nt2 * 16 + (((lane >> 4) & 1) << 3) + (lane & 7);
                int koff = ks * 16 + (((lane >> 3) & 1) << 3);
                ldsm_x4(bf[nt2][0], bf[nt2][1], bf[nt2][2], bf[nt2][3],
                        sB + row * 272 + koff * 2);
            }
            #pragma unroll
            for (int mt = 0; mt < 2; mt++)
                #pragma unroll
                for (int nt = 0; nt < 4; nt++)
                    mma_bf16(acc[mt][nt], af[mt],
                             bf[nt >> 1][(nt & 1) * 2], bf[nt >> 1][(nt & 1) * 2 + 1]);
        }
    }

    int lr = lane >> 2;
    int lc = (lane & 3) * 2;
    #pragma unroll
    for (int mt = 0; mt < 2; mt++) {
        int r0 = mBase + wm * 32 + mt * 16 + lr;
        #pragma unroll
        for (int nt = 0; nt < 4; nt++) {
            int col = nBase + wn * 32 + nt * 8 + lc;
            __nv_bfloat162 pa = __floats2bfloat162_rn(acc[mt][nt][0], acc[mt][nt][1]);
            __nv_bfloat162 pb = __floats2bfloat162_rn(acc[mt][nt][2], acc[mt][nt][3]);
            *(__nv_bfloat162*)(D + (size_t)r0 * 384 + col)       = pa;
            *(__nv_bfloat162*)(D + (size_t)(r0 + 8) * 384 + col) = pb;
        }
    }
}

// ---------------------------------------------------------------------------
// proj + LN2 fused, v3 (R12): M-tile 64, 8 warps (2m x 4n), 32-reg acc
// kept live through the LN output phase.
// ---------------------------------------------------------------------------
__global__ __launch_bounds__(256, 3) void proj_ln_kernel(
    const __nv_bfloat16* __restrict__ A, const __nv_bfloat16* __restrict__ Bt,
    float* __restrict__ D,
    const float* __restrict__ bias, const float* __restrict__ res,
    const float* __restrict__ n2g, const float* __restrict__ n2b,
    __nv_bfloat16* __restrict__ ln_out)
{
    __shared__ __align__(16) char smA[64 * 272];
    __shared__ __align__(16) char smB[128 * 272];
    __shared__ float2 red[64][4];

    int tid = threadIdx.x;
    int warp = tid >> 5;
    int lane = tid & 31;
    int wm = warp >> 2;
    int wn = warp & 3;
    int mBase = blockIdx.y * 64;

    uint32_t sA = smem_u32(smA);
    uint32_t sB = smem_u32(smB);

    #pragma unroll
    for (int kh = 0; kh < 2; kh++) {
        #pragma unroll
        for (int it = 0; it < 2; it++) {   // A half: 512 cp16
            int idx = it * 256 + tid;
            int r = idx >> 3, c = idx & 7;
            cp16(sA + r * 272 + kh * 128 + c * 16,
                 A + (size_t)(mBase + r) * 128 + kh * 64 + c * 8);
        }
        #pragma unroll
        for (int it = 0; it < 4; it++) {   // B half: 1024 cp16
            int idx = it * 256 + tid;
            int r = idx >> 3, c = idx & 7;
            cp16(sB + r * 272 + kh * 128 + c * 16,
                 Bt + (size_t)r * 128 + kh * 64 + c * 8);
        }
        CP_COMMIT();
    }

    float acc[2][4][4];
    #pragma unroll
    for (int i = 0; i < 2; i++)
        #pragma unroll
        for (int j = 0; j < 4; j++)
            #pragma unroll
            for (int q = 0; q < 4; q++) acc[i][j][q] = 0.0f;

    #pragma unroll
    for (int kh = 0; kh < 2; kh++) {
        if (kh == 0) CP_WAIT1(); else CP_WAIT0();
        __syncthreads();
        #pragma unroll
        for (int ki = 0; ki < 4; ki++) {
            int ks = kh * 4 + ki;
            uint32_t af[2][4];
            #pragma unroll
            for (int mt = 0; mt < 2; mt++) {
                int row = wm * 32 + mt * 16 + (lane & 15);
                int koff = ks * 16 + ((lane >> 4) << 3);
                ldsm_x4(af[mt][0], af[mt][1], af[mt][2], af[mt][3],
                        sA + row * 272 + koff * 2);
            }
            uint32_t bf[2][4];
            #pragma unroll
            for (int nt2 = 0; nt2 < 2; nt2++) {
                int row = wn * 32 + nt2 * 16 + (((lane >> 4) & 1) << 3) + (lane & 7);
                int koff = ks * 16 + (((lane >> 3) & 1) << 3);
                ldsm_x4(bf[nt2][0], bf[nt2][1], bf[nt2][2], bf[nt2][3],
                        sB + row * 272 + koff * 2);
            }
            #pragma unroll
            for (int mt = 0; mt < 2; mt++)
                #pragma unroll
                for (int nt = 0; nt < 4; nt++)
                    mma_bf16(acc[mt][nt], af[mt],
                             bf[nt >> 1][(nt & 1) * 2], bf[nt >> 1][(nt & 1) * 2 + 1]);
        }
    }

    int lr = lane >> 2;
    int lc = (lane & 3) * 2;

    float s1[2][2], s2[2][2];
    #pragma unroll
    for (int mt = 0; mt < 2; mt++)
        s1[mt][0] = s1[mt][1] = s2[mt][0] = s2[mt][1] = 0.0f;
    #pragma unroll
    for (int mt = 0; mt < 2; mt++) {
        int r0 = mBase + wm * 32 + mt * 16 + lr;
        #pragma unroll
        for (int nt = 0; nt < 4; nt++) {
            int col = wn * 32 + nt * 8 + lc;
            float2 bb = *(const float2*)(bias + col);
            float2 ra = *(const float2*)(res + (size_t)r0 * 128 + col);
            float2 rb = *(const float2*)(res + (size_t)(r0 + 8) * 128 + col);
            float v0 = acc[mt][nt][0] + bb.x + ra.x;
            float v1 = acc[mt][nt][1] + bb.y + ra.y;
            float v2 = acc[mt][nt][2] + bb.x + rb.x;
            float v3 = acc[mt][nt][3] + bb.y + rb.y;
            acc[mt][nt][0] = v0; acc[mt][nt][1] = v1;
            acc[mt][nt][2] = v2; acc[mt][nt][3] = v3;
            *(float2*)(D + (size_t)r0 * 128 + col)       = make_float2(v0, v1);
            *(float2*)(D + (size_t)(r0 + 8) * 128 + col) = make_float2(v2, v3);
            s1[mt][0] += v0 + v1;        s2[mt][0] += v0 * v0 + v1 * v1;
            s1[mt][1] += v2 + v3;        s2[mt][1] += v2 * v2 + v3 * v3;
        }
    }
    #pragma unroll
    for (int o = 1; o <= 2; o <<= 1) {
        #pragma unroll
        for (int mt = 0; mt < 2; mt++) {
            #pragma unroll
            for (int h = 0; h < 2; h++) {
                s1[mt][h] += __shfl_xor_sync(0xffffffffu, s1[mt][h], o);
                s2[mt][h] += __shfl_xor_sync(0xffffffffu, s2[mt][h], o);
            }
        }
    }
    if ((lane & 3) == 0) {
        #pragma unroll
        for (int mt = 0; mt < 2; mt++)
            #pragma unroll
            for (int h = 0; h < 2; h++)
                red[wm * 32 + mt * 16 + h * 8 + lr][wn] =
                    make_float2(s1[mt][h], s2[mt][h]);
    }
    __syncthreads();

    #pragma unroll
    for (int mt = 0; mt < 2; mt++) {
        #pragma unroll
        for (int h = 0; h < 2; h++) {
            int rl = wm * 32 + mt * 16 + h * 8 + lr;
            float2 r0v = red[rl][0];
            float2 r1v = red[rl][1];
            float2 r2v = red[rl][2];
            float2 r3v = red[rl][3];
            float mu = (r0v.x + r1v.x + r2v.x + r3v.x) * (1.0f / 128.0f);
            float var = (r0v.y + r1v.y + r2v.y + r3v.y) * (1.0f / 128.0f) - mu * mu;
            float rs = rsqrtf(var + 1e-5f);
            __nv_bfloat16* op = ln_out + (size_t)(mBase + rl) * 128;
            #pragma unroll
            for (int nt = 0; nt < 4; nt++) {
                int col = wn * 32 + nt * 8 + lc;
                float2 gg = *(const float2*)(n2g + col);
                float2 bb = *(const float2*)(n2b + col);
                float v0 = acc[mt][nt][h * 2];
                float v1 = acc[mt][nt][h * 2 + 1];
                float l0 = (v0 - mu) * rs * gg.x + bb.x;
                float l1 = (v1 - mu) * rs * gg.y + bb.y;
                __nv_bfloat162 pr = __floats2bfloat162_rn(l0, l1);
                *(__nv_bfloat162*)(op + col) = pr;
            }
        }
    }
}

// ---------------------------------------------------------------------------
// Fused MLP v2 (unchanged): double-buffered weight chunks.
// ---------------------------------------------------------------------------
#define AOFF  0
#define HOFF  17408
#define W1OFF 26624
#define W2OFF 61440
#define W1SZ  17408          // 64 * 272
#define W2SZ  18432          // 128 * 144
#define MLP_SMEM 98304

__global__ __launch_bounds__(256, 2) void mlp_kernel(
    const __nv_bfloat16* __restrict__ Aln, const __nv_bfloat16* __restrict__ W1t,
    const __nv_bfloat16* __restrict__ W2t, float* __restrict__ out,
    const float* __restrict__ b1, const float* __restrict__ b2,
    const float* __restrict__ res)
{
    extern __shared__ __align__(16) char dsm[];
    uint32_t sbase = smem_u32(dsm);

    int tid = threadIdx.x;
    int warp = tid >> 5;
    int lane = tid & 31;
    int wm = warp >> 2;
    int wn = warp & 3;
    int mBase = blockIdx.y * 64;
    int lr = lane >> 2;
    int lc = (lane & 3) * 2;

    auto issueW = [&](int h) {
        int buf = h & 1;
        #pragma unroll
        for (int it = 0; it < 4; it++) {
            int idx = it * 256 + tid;
            int r = idx >> 4, c = idx & 15;
            cp16(sbase + W1OFF + buf * W1SZ + r * 272 + c * 16,
                 W1t + (size_t)(h * 64 + r) * 128 + c * 8);
        }
        #pragma unroll
        for (int it = 0; it < 4; it++) {
            int idx = it * 256 + tid;
            int r = idx >> 3, c = idx & 7;
            cp16(sbase + W2OFF + buf * W2SZ + r * 144 + c * 16,
                 W2t + (size_t)r * 512 + h * 64 + c * 8);
        }
    };

    #pragma unroll
    for (int it = 0; it < 4; it++) {
        int idx = it * 256 + tid;
        int r = idx >> 4, c = idx & 15;
        cp16(sbase + AOFF + r * 272 + c * 16,
             Aln + (size_t)(mBase + r) * 128 + c * 8);
    }
    issueW(0);
    CP_COMMIT();

    float acc2[2][4][4];
    #pragma unroll
    for (int i = 0; i < 2; i++)
        #pragma unroll
        for (int j = 0; j < 4; j++)
            #pragma unroll
            for (int q = 0; q < 4; q++) acc2[i][j][q] = 0.0f;

    for (int h = 0; h < 8; h++) {
        if (h + 1 < 8) {
            issueW(h + 1);
            CP_COMMIT();
            CP_WAIT1();
        } else {
            CP_WAIT0();
        }
        __syncthreads();

        uint32_t w1b = sbase + W1OFF + (h & 1) * W1SZ;
        uint32_t w2b = sbase + W2OFF + (h & 1) * W2SZ;

        float acc1[2][2][4];
        #pragma unroll
        for (int i = 0; i < 2; i++)
            #pragma unroll
            for (int j = 0; j < 2; j++)
                #pragma unroll
                for (int q = 0; q < 4; q++) acc1[i][j][q] = 0.0f;

        #pragma unroll
        for (int ks = 0; ks < 8; ks++) {
            uint32_t af[2][4];
            #pragma unroll
            for (int mt = 0; mt < 2; mt++) {
                int row = wm * 32 + mt * 16 + (lane & 15);
                int koff = ks * 16 + ((lane >> 4) << 3);
                ldsm_x4(af[mt][0], af[mt][1], af[mt][2], af[mt][3],
                        sbase + AOFF + row * 272 + koff * 2);
            }
            uint32_t bf1[4];
            {
                int row = wn * 16 + (((lane >> 4) & 1) << 3) + (lane & 7);
                int koff = ks * 16 + (((lane >> 3) & 1) << 3);
                ldsm_x4(bf1[0], bf1[1], bf1[2], bf1[3], w1b + row * 272 + koff * 2);
            }
            #pragma unroll
            for (int mt = 0; mt < 2; mt++)
                #pragma unroll
                for (int nt = 0; nt < 2; nt++)
                    mma_bf16(acc1[mt][nt], af[mt], bf1[nt * 2], bf1[nt * 2 + 1]);
        }

        #pragma unroll
        for (int mt = 0; mt < 2; mt++) {
            int row0 = wm * 32 + mt * 16 + lr;
            #pragma unroll
            for (int nt = 0; nt < 2; nt++) {
                int cc = wn * 16 + nt * 8 + lc;
                float2 bb = *(const float2*)(b1 + h * 64 + cc);
                float v0 = acc1[mt][nt][0] + bb.x;
                float v1 = acc1[mt][nt][1] + bb.y;
                float v2 = acc1[mt][nt][2] + bb.x;
                float v3 = acc1[mt][nt][3] + bb.y;
                v0 = 0.5f * v0 * (1.0f + erff(v0 * 0.70710678118654752f));
                v1 = 0.5f * v1 * (1.0f + erff(v1 * 0.70710678118654752f));
                v2 = 0.5f * v2 * (1.0f + erff(v2 * 0.70710678118654752f));
                v3 = 0.5f * v3 * (1.0f + erff(v3 * 0.70710678118654752f));
                __nv_bfloat162 pa = __floats2bfloat162_rn(v0, v1);
                __nv_bfloat162 pb = __floats2bfloat162_rn(v2, v3);
                *(__nv_bfloat162*)(dsm + HOFF + row0 * 144 + cc * 2) = pa;
                *(__nv_bfloat162*)(dsm + HOFF + (row0 + 8) * 144 + cc * 2) = pb;
            }
        }
        __syncthreads();

        #pragma unroll
        for (int ks = 0; ks < 4; ks++) {
            uint32_t af[2][4];
            #pragma unroll
            for (int mt = 0; mt < 2; mt++) {
                int row = wm * 32 + mt * 16 + (lane & 15);
                int koff = ks * 16 + ((lane >> 4) << 3);
                ldsm_x4(af[mt][0], af[mt][1], af[mt][2], af[mt][3],
                        sbase + HOFF + row * 144 + koff * 2);
            }
            uint32_t bf2[2][4];
            #pragma unroll
            for (int nt2 = 0; nt2 < 2; nt2++) {
                int row = wn * 32 + nt2 * 16 + (((lane >> 4) & 1) << 3) + (lane & 7);
                int koff = ks * 16 + (((lane >> 3) & 1) << 3);
                ldsm_x4(bf2[nt2][0], bf2[nt2][1], bf2[nt2][2], bf2[nt2][3],
                        w2b + row * 144 + koff * 2);
            }
            #pragma unroll
            for (int mt = 0; mt < 2; mt++)
                #pragma unroll
                for (int nt = 0; nt < 4; nt++)
                    mma_bf16(acc2[mt][nt], af[mt],
                             bf2[nt >> 1][(nt & 1) * 2], bf2[nt >> 1][(nt & 1) * 2 + 1]);
        }
        __syncthreads();
    }

    #pragma unroll
    for (int mt = 0; mt < 2; mt++) {
        int r0 = mBase + wm * 32 + mt * 16 + lr;
        #pragma unroll
        for (int nt = 0; nt < 4; nt++) {
            int col = wn * 32 + nt * 8 + lc;
            float2 bb = *(const float2*)(b2 + col);
            float2 ra = *(const float2*)(res + (size_t)r0 * 128 + col);
            float2 rb = *(const float2*)(res + (size_t)(r0 + 8) * 128 + col);
            *(float2*)(out + (size_t)r0 * 128 + col) =
                make_float2(acc2[mt][nt][0] + bb.x + ra.x,
                            acc2[mt][nt][1] + bb.y + ra.y);
            *(float2*)(out + (size_t)(r0 + 8) * 128 + col) =
                make_float2(acc2[mt][nt][2] + bb.x + rb.x,
                            acc2[mt][nt][3] + bb.y + rb.y);
        }
    }
}

// ---------------------------------------------------------------------------
// Flash-style HMMA window attention + fused LEPE, templated on branch (R12).
// One block per (branch, window, head): 3584 blocks, 224 threads (7 warps).
// ---------------------------------------------------------------------------
#define AROW 80   // bytes per smem row in attention tiles (40 bf16)

template<int BRANCH>
__device__ __forceinline__ void attn_body(
    const __nv_bfloat16* __restrict__ qkv,
    const float* __restrict__ cw0, const float* __restrict__ cb0,
    const float* __restrict__ cw1, const float* __restrict__ cb1,
    __nv_bfloat16* __restrict__ outp,
    char* smQc, char* smKc, char* smVc, float* cwS, float* cbS,
    int rem)
{
    constexpr int Hsp = BRANCH ? 2 : RESO_;
    constexpr int Wsp = BRANCH ? RESO_ : 2;

    int win = rem >> 1;
    int head = rem & 1;
    int b = win / NWIN_;
    int slot = win - b * NWIN_;
    int cb = BRANCH * 64 + head * 32;
    int tid = threadIdx.x;
    int warp = tid >> 5;
    int lane = tid & 31;
    const float kscale = 0.17677669529663687f * 1.4426950408889634f;

    uint32_t sQ = smem_u32(smQc);
    uint32_t sK = smem_u32(smKc);
    uint32_t sV = smem_u32(smVc);

    {
        const float* cw = (BRANCH ? cw1 : cw0) + head * 32 * 9;
        const float* cbp = (BRANCH ? cb1 : cb0) + head * 32;
        for (int i = tid; i < 288; i += 224) {
            int d = i / 9, wi = i - d * 9;
            cwS[wi * 32 + d] = cw[i];
        }
        if (tid < 32) cbS[tid] = cbp[tid];
    }

    #pragma unroll
    for (int tile = 0; tile < 3; tile++) {
        char* dst = (tile == 0 ? smQc : tile == 1 ? smKc : smVc);
        #pragma unroll
        for (int it = 0; it < 2; it++) {
            int idx = it * 224 + tid;
            int t = idx >> 2;
            int f = idx & 3;
            int pix;
            if (BRANCH == 0) {
                pix = (t >> 1) * RESO_ + slot * 2 + (t & 1);
            } else {
                int hs = (t >= RESO_) ? 1 : 0;
                pix = (slot * 2 + hs) * RESO_ + (t - hs * RESO_);
            }
            size_t ro = ((size_t)(b * L_ + pix)) * 384 + cb + tile * 128 + f * 8;
            *(uint4*)(dst + t * AROW + f * 16) = *(const uint4*)(qkv + ro);
        }
    }
    __syncthreads();

    uint32_t af[2][4];
    #pragma unroll
    for (int kt = 0; kt < 2; kt++) {
        int row = warp * 16 + (lane & 15);
        int koff = kt * 16 + ((lane >> 4) << 3);
        ldsm_x4(af[kt][0], af[kt][1], af[kt][2], af[kt][3],
                sQ + row * AROW + koff * 2);
    }

    float s[14][4];
    #pragma unroll
    for (int nt = 0; nt < 14; nt++) {
        s[nt][0] = s[nt][1] = s[nt][2] = s[nt][3] = 0.0f;
        uint32_t kb[4];
        ldsm_x4(kb[0], kb[1], kb[2], kb[3],
                sK + (nt * 8 + (lane & 7)) * AROW + (lane >> 3) * 16);
        mma_bf16(s[nt], af[0], kb[0], kb[1]);
        mma_bf16(s[nt], af[1], kb[2], kb[3]);
    }

    float m0 = -1e30f, m1 = -1e30f;
    #pragma unroll
    for (int nt = 0; nt < 14; nt++) {
        m0 = fmaxf(m0, fmaxf(s[nt][0], s[nt][1]));
        m1 = fmaxf(m1, fmaxf(s[nt][2], s[nt][3]));
    }
    #pragma unroll
    for (int o = 1; o <= 2; o <<= 1) {
        m0 = fmaxf(m0, __shfl_xor_sync(0xffffffffu, m0, o));
        m1 = fmaxf(m1, __shfl_xor_sync(0xffffffffu, m1, o));
    }
    float m0k = m0 * kscale;
    float m1k = m1 * kscale;
    float sum0 = 0.0f, sum1 = 0.0f;
    uint32_t p01[14], p23[14];
    #pragma unroll
    for (int nt = 0; nt < 14; nt++) {
        float e0 = exp2f(fmaf(s[nt][0], kscale, -m0k));
        float e1 = exp2f(fmaf(s[nt][1], kscale, -m0k));
        float e2 = exp2f(fmaf(s[nt][2], kscale, -m1k));
        float e3 = exp2f(fmaf(s[nt][3], kscale, -m1k));
        sum0 += e0 + e1;
        sum1 += e2 + e3;
        __nv_bfloat162 pa = __floats2bfloat162_rn(e0, e1);
        __nv_bfloat162 pb = __floats2bfloat162_rn(e2, e3);
        p01[nt] = *reinterpret_cast<uint32_t*>(&pa);
        p23[nt] = *reinterpret_cast<uint32_t*>(&pb);
    }
    #pragma unroll
    for (int o = 1; o <= 2; o <<= 1) {
        sum0 += __shfl_xor_sync(0xffffffffu, sum0, o);
        sum1 += __shfl_xor_sync(0xffffffffu, sum1, o);
    }
    float inv0 = 1.0f / sum0;
    float inv1 = 1.0f / sum1;

    float oacc[4][4];
    #pragma unroll
    for (int nt = 0; nt < 4; nt++)
        oacc[nt][0] = oacc[nt][1] = oacc[nt][2] = oacc[nt][3] = 0.0f;

    #pragma unroll
    for (int kt = 0; kt < 7; kt++) {
        uint32_t pa[4] = {p01[2 * kt], p23[2 * kt], p01[2 * kt + 1], p23[2 * kt + 1]};
        uint32_t vb[4], vb2[4];
        uint32_t vaddr = sV + (kt * 16 + (lane & 15)) * AROW + (lane >> 4) * 16;
        ldsm_x4_t(vb[0],  vb[1],  vb[2],  vb[3],  vaddr);
        ldsm_x4_t(vb2[0], vb2[1], vb2[2], vb2[3], vaddr + 32);
        mma_bf16(oacc[0], pa, vb[0],  vb[1]);
        mma_bf16(oacc[1], pa, vb[2],  vb[3]);
        mma_bf16(oacc[2], pa, vb2[0], vb2[1]);
        mma_bf16(oacc[3], pa, vb2[2], vb2[3]);
    }

    const __nv_bfloat16* Vbf = (const __nv_bfloat16*)smVc;
    int lr = lane >> 2;
    int lc = (lane & 3) * 2;

    #pragma unroll
    for (int half = 0; half < 2; half++) {
        int tok = warp * 16 + lr + half * 8;
        float inv = half ? inv1 : inv0;
        int hs, ws;
        if (BRANCH == 0) { hs = tok >> 1; ws = tok & 1; }
        else             { hs = (tok >= RESO_) ? 1 : 0; ws = tok - hs * RESO_; }

        float l[8];
        #pragma unroll
        for (int nt = 0; nt < 4; nt++) {
            l[nt * 2]     = cbS[nt * 8 + lc];
            l[nt * 2 + 1] = cbS[nt * 8 + lc + 1];
        }
        #pragma unroll
        for (int wi = 0; wi < 9; wi++) {
            int dy = wi / 3 - 1, dx = wi - (wi / 3) * 3 - 1;
            int y = hs + dy, x = ws + dx;
            if (y >= 0 && y < Hsp && x >= 0 && x < Wsp) {
                const __nv_bfloat16* vp = Vbf + (y * Wsp + x) * 40;
                const float* wp = cwS + wi * 32;
                #pragma unroll
                for (int nt = 0; nt < 4; nt++) {
                    int d0 = nt * 8 + lc;
                    float2 vv = __bfloat1622float2(*(const __nv_bfloat162*)(vp + d0));
                    l[nt * 2]     += wp[d0]     * vv.x;
                    l[nt * 2 + 1] += wp[d0 + 1] * vv.y;
                }
            }
        }

        int pix;
        if (BRANCH == 0) pix = hs * RESO_ + slot * 2 + ws;
        else             pix = (slot * 2 + hs) * RESO_ + ws;
        __nv_bfloat16* op = outp + ((size_t)(b * L_ + pix)) * C_ + cb;

        #pragma unroll
        for (int nt = 0; nt < 4; nt++) {
            float v0 = oacc[nt][half * 2]     * inv + l[nt * 2];
            float v1 = oacc[nt][half * 2 + 1] * inv + l[nt * 2 + 1];
            __nv_bfloat162 pr = __floats2bfloat162_rn(v0, v1);
            *(__nv_bfloat162*)(op + nt * 8 + lc) = pr;
        }
    }
}

__global__ __launch_bounds__(224, 4) void attn_kernel(
    const __nv_bfloat16* __restrict__ qkv,
    const float* __restrict__ cw0, const float* __restrict__ cb0,
    const float* __restrict__ cw1, const float* __restrict__ cb1,
    __nv_bfloat16* __restrict__ outp)
{
    __shared__ __align__(16) char smQ[TOK_ * AROW];
    __shared__ __align__(16) char smK[TOK_ * AROW];
    __shared__ __align__(16) char smV[TOK_ * AROW];
    __shared__ float cwS[288];
    __shared__ float cbS[32];

    int bid = blockIdx.x;
    if (bid < 1792)
        attn_body<0>(qkv, cw0, cb0, cw1, cb1, outp, smQ, smK, smV, cwS, cbS, bid);
    else
        attn_body<1>(qkv, cw0, cb0, cw1, cb1, outp, smQ, smK, smV, cwS, cbS, bid - 1792);
}

// ---------------------------------------------------------------------------
extern "C" void kernel_launch(void* const* d_in, const int* in_sizes, int n_in,
                              void* d_out, int out_size)
{
    const float* x       = (const float*)d_in[0];
    const float* n1g     = (const float*)d_in[1];
    const float* n1b     = (const float*)d_in[2];
    const float* qkv_w   = (const float*)d_in[3];
    const float* proj_w  = (const float*)d_in[4];
    const float* proj_b  = (const float*)d_in[5];
    const float* conv_w0 = (const float*)d_in[6];
    const float* conv_b0 = (const float*)d_in[7];
    const float* conv_w1 = (const float*)d_in[8];
    const float* conv_b1 = (const float*)d_in[9];
    const float* n2g     = (const float*)d_in[10];
    const float* n2b     = (const float*)d_in[11];
    const float* fc1_w   = (const float*)d_in[12];
    const float* fc1_b   = (const float*)d_in[13];
    const float* fc2_w   = (const float*)d_in[14];
    const float* fc2_b   = (const float*)d_in[15];
    float* out = (float*)d_out;

    __nv_bfloat16 *ln, *qkvb, *attn, *wts;
    float *xr;
    cudaGetSymbolAddress((void**)&ln,   g_ln);
    cudaGetSymbolAddress((void**)&qkvb, g_qkv);
    cudaGetSymbolAddress((void**)&attn, g_attn);
    cudaGetSymbolAddress((void**)&xr,   g_x);
    cudaGetSymbolAddress((void**)&wts,  g_w);

    __nv_bfloat16* w_qkv = wts;                 // [384,128]
    __nv_bfloat16* w_prj = wts + 49152;         // [128,128]
    __nv_bfloat16* w_fc1 = wts + 65536;         // [512,128]
    __nv_bfloat16* w_fc2 = wts + 131072;        // [128,512]

    cudaFuncSetAttribute(mlp_kernel,
                         cudaFuncAttributeMaxDynamicSharedMemorySize, MLP_SMEM);

    // 1. LN1 -> bf16 (+ folded weight convert in first 768 blocks)
    ln_conv_kernel<<<M_ / 8, 256>>>(x, n1g, n1b, ln,
                                    qkv_w, proj_w, fc1_w, fc2_w, wts);
    // 2. QKV GEMM (one-shot M64 tiles) -> bf16
    qkv_gemm_kernel<<<dim3(3, M_ / 64), 256>>>(ln, w_qkv, qkvb);
    // 3. Flash-style HMMA window attention + LEPE -> bf16
    attn_kernel<<<3584, 224>>>(qkvb, conv_w0, conv_b0, conv_w1, conv_b1, attn);
    // 4. proj GEMM + bias + residual(x) -> fp32 xr, fused LN2 -> bf16 ln
    proj_ln_kernel<<<dim3(1, M_ / 64), 256>>>(attn, w_prj, xr,
                                              proj_b, x, n2g, n2b, ln);
    // 5. fused MLP (double-buffered): GELU(ln@W1+b1)@W2 + b2 + xr -> fp32 out
    mlp_kernel<<<dim3(1, M_ / 64), 256, MLP_SMEM>>>(ln, w_fc1, w_fc2, out,
                                                    fc1_b, fc2_b, xr);
}

// round 16
// speedup vs baseline: 1.0226x; 1.0226x over previous
#include <cuda_runtime.h>
#include <cuda_bf16.h>
#include <math.h>
#include <stdint.h>

// Problem constants
#define BATCH_ 32
#define RESO_ 56
#define L_ (RESO_ * RESO_)          // 3136
#define C_ 128
#define M_ (BATCH_ * L_)            // 100352 rows
#define HID_ 512
#define TOK_ 112                    // window tokens (56*2)
#define NWIN_ 28                    // windows per batch per branch

// Scratch buffers (device globals: allocation-free)
__device__ __nv_bfloat16 g_ln  [(size_t)M_ * C_];
__device__ __nv_bfloat16 g_qkv [(size_t)M_ * 3 * C_];
__device__ __nv_bfloat16 g_attn[(size_t)M_ * C_];
__device__ float         g_x   [(size_t)M_ * C_];
__device__ __nv_bfloat16 g_w   [196608];   // transposed bf16 weights

// ---------------------------------------------------------------------------
// PTX helpers (baseline PTX, portable to compute_103)
// ---------------------------------------------------------------------------
__device__ __forceinline__ uint32_t smem_u32(const void* p) {
    uint32_t a;
    asm("{ .reg .u64 t; cvta.to.shared.u64 t, %1; cvt.u32.u64 %0, t; }" : "=r"(a) : "l"(p));
    return a;
}
__device__ __forceinline__ void cp16(uint32_t dst, const void* src) {
    asm volatile("cp.async.cg.shared.global [%0], [%1], 16;" :: "r"(dst), "l"(src));
}
#define CP_COMMIT() asm volatile("cp.async.commit_group;" ::: "memory")
#define CP_WAIT1()  asm volatile("cp.async.wait_group 1;" ::: "memory")
#define CP_WAIT0()  asm volatile("cp.async.wait_group 0;" ::: "memory")

__device__ __forceinline__ void ldsm_x4(uint32_t& r0, uint32_t& r1,
                                        uint32_t& r2, uint32_t& r3, uint32_t addr) {
    asm volatile("ldmatrix.sync.aligned.m8n8.x4.shared.b16 {%0,%1,%2,%3}, [%4];"
                 : "=r"(r0), "=r"(r1), "=r"(r2), "=r"(r3) : "r"(addr));
}
__device__ __forceinline__ void ldsm_x4_t(uint32_t& r0, uint32_t& r1,
                                          uint32_t& r2, uint32_t& r3, uint32_t addr) {
    asm volatile("ldmatrix.sync.aligned.m8n8.x4.trans.shared.b16 {%0,%1,%2,%3}, [%4];"
                 : "=r"(r0), "=r"(r1), "=r"(r2), "=r"(r3) : "r"(addr));
}
__device__ __forceinline__ void mma_bf16(float* c, const uint32_t* a,
                                         uint32_t b0, uint32_t b1) {
    asm volatile("mma.sync.aligned.m16n8k16.row.col.f32.bf16.bf16.f32 "
                 "{%0,%1,%2,%3}, {%4,%5,%6,%7}, {%8,%9}, {%0,%1,%2,%3};"
                 : "+f"(c[0]), "+f"(c[1]), "+f"(c[2]), "+f"(c[3])
                 : "r"(a[0]), "r"(a[1]), "r"(a[2]), "r"(a[3]), "r"(b0), "r"(b1));
}

// ---------------------------------------------------------------------------
// LayerNorm (one warp per row) + folded weight convert/transpose in blocks<768.
// ---------------------------------------------------------------------------
__global__ __launch_bounds__(256) void ln_conv_kernel(
    const float* __restrict__ in, const float* __restrict__ g,
    const float* __restrict__ b, __nv_bfloat16* __restrict__ out,
    const float* __restrict__ qkv_w, const float* __restrict__ proj_w,
    const float* __restrict__ fc1_w, const float* __restrict__ fc2_w,
    __nv_bfloat16* __restrict__ wout)
{
    if (blockIdx.x < 768) {
        int i = blockIdx.x * 256 + threadIdx.x;
        float v;
        if (i < 49152) {
            int n = i >> 7, k = i & 127;
            v = qkv_w[(size_t)k * 384 + n];
        } else if (i < 65536) {
            int j = i - 49152;    int n = j >> 7, k = j & 127;
            v = proj_w[(size_t)k * 128 + n];
        } else if (i < 131072) {
            int j = i - 65536;    int n = j >> 7, k = j & 127;
            v = fc1_w[(size_t)k * 512 + n];
        } else {
            int j = i - 131072;   int n = j >> 9, k = j & 511;
            v = fc2_w[(size_t)k * 128 + n];
        }
        wout[i] = __float2bfloat16(v);
    }

    int warp = (blockIdx.x * blockDim.x + threadIdx.x) >> 5;
    int lane = threadIdx.x & 31;
    if (warp >= M_) return;
    float4 v = ((const float4*)(in + (size_t)warp * C_))[lane];
    float s = v.x + v.y + v.z + v.w;
    #pragma unroll
    for (int o = 16; o; o >>= 1) s += __shfl_xor_sync(0xffffffffu, s, o);
    float mu = s * (1.0f / C_);
    float dx = v.x - mu, dy = v.y - mu, dz = v.z - mu, dw = v.w - mu;
    float q = dx*dx + dy*dy + dz*dz + dw*dw;
    #pragma unroll
    for (int o = 16; o; o >>= 1) q += __shfl_xor_sync(0xffffffffu, q, o);
    float rs = rsqrtf(q * (1.0f / C_) + 1e-5f);
    float4 gg = ((const float4*)g)[lane];
    float4 bb = ((const float4*)b)[lane];
    __nv_bfloat162 p0 = __floats2bfloat162_rn(dx * rs * gg.x + bb.x, dy * rs * gg.y + bb.y);
    __nv_bfloat162 p1 = __floats2bfloat162_rn(dz * rs * gg.z + bb.z, dw * rs * gg.w + bb.w);
    uint2 u;
    u.x = *reinterpret_cast<uint32_t*>(&p0);
    u.y = *reinterpret_cast<uint32_t*>(&p1);
    ((uint2*)(out + (size_t)warp * C_))[lane] = u;
}

// ---------------------------------------------------------------------------
// Lean chunked bf16 HMMA GEMM (R4 version): qkv only. mode 0: write bf16.
// ---------------------------------------------------------------------------
#define ROWB 80   // bytes per padded smem row (40 bf16)

__global__ __launch_bounds__(256) void mma_gemm_kernel(
    const __nv_bfloat16* __restrict__ A, const __nv_bfloat16* __restrict__ Bt,
    void* __restrict__ D, int N, int K,
    const float* __restrict__ bias, const float* __restrict__ res, int mode)
{
    __shared__ __align__(16) char smA[2][128 * ROWB];
    __shared__ __align__(16) char smB[2][128 * ROWB];

    int tid = threadIdx.x;
    int warp = tid >> 5;
    int lane = tid & 31;
    int wm = warp >> 1;
    int wn = warp & 1;
    int mBase = blockIdx.y * 128;
    int nBase = blockIdx.x * 128;

    uint32_t sA = smem_u32(smA);
    uint32_t sB = smem_u32(smB);

    float acc[2][8][4];
    #pragma unroll
    for (int i = 0; i < 2; i++)
        #pragma unroll
        for (int j = 0; j < 8; j++)
            #pragma unroll
            for (int q = 0; q < 4; q++) acc[i][j][q] = 0.0f;

    int nkt = K >> 5;

    auto issue = [&](int kt) {
        int buf = kt & 1;
        #pragma unroll
        for (int it = 0; it < 2; it++) {
            int idx = it * 256 + tid;
            int r = idx >> 2, c = idx & 3;
            const __nv_bfloat16* ga = A  + (size_t)(mBase + r) * K + kt * 32 + c * 8;
            const __nv_bfloat16* gb = Bt + (size_t)(nBase + r) * K + kt * 32 + c * 8;
            uint32_t off = (uint32_t)(r * ROWB + c * 16);
            cp16(sA + buf * (128 * ROWB) + off, ga);
            cp16(sB + buf * (128 * ROWB) + off, gb);
        }
    };

    issue(0);
    CP_COMMIT();

    for (int kt = 0; kt < nkt; kt++) {
        if (kt + 1 < nkt) {
            issue(kt + 1);
            CP_COMMIT();
            CP_WAIT1();
        } else {
            CP_WAIT0();
        }
        __syncthreads();

        uint32_t aB = sA + (kt & 1) * (128 * ROWB);
        uint32_t bB = sB + (kt & 1) * (128 * ROWB);

        #pragma unroll
        for (int ks = 0; ks < 2; ks++) {
            uint32_t af[2][4];
            #pragma unroll
            for (int mt = 0; mt < 2; mt++) {
                int row = wm * 32 + mt * 16 + (lane & 15);
                int koff = ks * 16 + ((lane >> 4) << 3);
                ldsm_x4(af[mt][0], af[mt][1], af[mt][2], af[mt][3],
                        aB + row * ROWB + koff * 2);
            }
            uint32_t bf[4][4];
            #pragma unroll
            for (int nt2 = 0; nt2 < 4; nt2++) {
                int row = wn * 64 + nt2 * 16 + (((lane >> 4) & 1) << 3) + (lane & 7);
                int koff = ks * 16 + (((lane >> 3) & 1) << 3);
                ldsm_x4(bf[nt2][0], bf[nt2][1], bf[nt2][2], bf[nt2][3],
                        bB + row * ROWB + koff * 2);
            }
            #pragma unroll
            for (int mt = 0; mt < 2; mt++)
                #pragma unroll
                for (int nt = 0; nt < 8; nt++)
                    mma_bf16(acc[mt][nt], af[mt],
                             bf[nt >> 1][(nt & 1) * 2], bf[nt >> 1][(nt & 1) * 2 + 1]);
        }
        __syncthreads();
    }

    int lr = lane >> 2;
    int lc = (lane & 3) * 2;
    #pragma unroll
    for (int mt = 0; mt < 2; mt++) {
        int r0 = mBase + wm * 32 + mt * 16 + lr;
        #pragma unroll
        for (int nt = 0; nt < 8; nt++) {
            int col = nBase + wn * 64 + nt * 8 + lc;
            __nv_bfloat16* op = (__nv_bfloat16*)D;
            __nv_bfloat162 pa = __floats2bfloat162_rn(acc[mt][nt][0], acc[mt][nt][1]);
            __nv_bfloat162 pb = __floats2bfloat162_rn(acc[mt][nt][2], acc[mt][nt][3]);
            *(__nv_bfloat162*)(op + (size_t)r0 * N + col)       = pa;
            *(__nv_bfloat162*)(op + (size_t)(r0 + 8) * N + col) = pb;
        }
    }
}

// ---------------------------------------------------------------------------
// proj + LN2 fused, v3 (R12): M-tile 64, 8 warps (2m x 4n), 32-reg acc
// kept live through the LN output phase.
// ---------------------------------------------------------------------------
__global__ __launch_bounds__(256, 3) void proj_ln_kernel(
    const __nv_bfloat16* __restrict__ A, const __nv_bfloat16* __restrict__ Bt,
    float* __restrict__ D,
    const float* __restrict__ bias, const float* __restrict__ res,
    const float* __restrict__ n2g, const float* __restrict__ n2b,
    __nv_bfloat16* __restrict__ ln_out)
{
    __shared__ __align__(16) char smA[64 * 272];
    __shared__ __align__(16) char smB[128 * 272];
    __shared__ float2 red[64][4];

    int tid = threadIdx.x;
    int warp = tid >> 5;
    int lane = tid & 31;
    int wm = warp >> 2;
    int wn = warp & 3;
    int mBase = blockIdx.y * 64;

    uint32_t sA = smem_u32(smA);
    uint32_t sB = smem_u32(smB);

    #pragma unroll
    for (int kh = 0; kh < 2; kh++) {
        #pragma unroll
        for (int it = 0; it < 2; it++) {   // A half: 512 cp16
            int idx = it * 256 + tid;
            int r = idx >> 3, c = idx & 7;
            cp16(sA + r * 272 + kh * 128 + c * 16,
                 A + (size_t)(mBase + r) * 128 + kh * 64 + c * 8);
        }
        #pragma unroll
        for (int it = 0; it < 4; it++) {   // B half: 1024 cp16
            int idx = it * 256 + tid;
            int r = idx >> 3, c = idx & 7;
            cp16(sB + r * 272 + kh * 128 + c * 16,
                 Bt + (size_t)r * 128 + kh * 64 + c * 8);
        }
        CP_COMMIT();
    }

    float acc[2][4][4];
    #pragma unroll
    for (int i = 0; i < 2; i++)
        #pragma unroll
        for (int j = 0; j < 4; j++)
            #pragma unroll
            for (int q = 0; q < 4; q++) acc[i][j][q] = 0.0f;

    #pragma unroll
    for (int kh = 0; kh < 2; kh++) {
        if (kh == 0) CP_WAIT1(); else CP_WAIT0();
        __syncthreads();
        #pragma unroll
        for (int ki = 0; ki < 4; ki++) {
            int ks = kh * 4 + ki;
            uint32_t af[2][4];
            #pragma unroll
            for (int mt = 0; mt < 2; mt++) {
                int row = wm * 32 + mt * 16 + (lane & 15);
                int koff = ks * 16 + ((lane >> 4) << 3);
                ldsm_x4(af[mt][0], af[mt][1], af[mt][2], af[mt][3],
                        sA + row * 272 + koff * 2);
            }
            uint32_t bf[2][4];
            #pragma unroll
            for (int nt2 = 0; nt2 < 2; nt2++) {
                int row = wn * 32 + nt2 * 16 + (((lane >> 4) & 1) << 3) + (lane & 7);
                int koff = ks * 16 + (((lane >> 3) & 1) << 3);
                ldsm_x4(bf[nt2][0], bf[nt2][1], bf[nt2][2], bf[nt2][3],
                        sB + row * 272 + koff * 2);
            }
            #pragma unroll
            for (int mt = 0; mt < 2; mt++)
                #pragma unroll
                for (int nt = 0; nt < 4; nt++)
                    mma_bf16(acc[mt][nt], af[mt],
                             bf[nt >> 1][(nt & 1) * 2], bf[nt >> 1][(nt & 1) * 2 + 1]);
        }
    }

    int lr = lane >> 2;
    int lc = (lane & 3) * 2;

    float s1[2][2], s2[2][2];
    #pragma unroll
    for (int mt = 0; mt < 2; mt++)
        s1[mt][0] = s1[mt][1] = s2[mt][0] = s2[mt][1] = 0.0f;
    #pragma unroll
    for (int mt = 0; mt < 2; mt++) {
        int r0 = mBase + wm * 32 + mt * 16 + lr;
        #pragma unroll
        for (int nt = 0; nt < 4; nt++) {
            int col = wn * 32 + nt * 8 + lc;
            float2 bb = *(const float2*)(bias + col);
            float2 ra = *(const float2*)(res + (size_t)r0 * 128 + col);
            float2 rb = *(const float2*)(res + (size_t)(r0 + 8) * 128 + col);
            float v0 = acc[mt][nt][0] + bb.x + ra.x;
            float v1 = acc[mt][nt][1] + bb.y + ra.y;
            float v2 = acc[mt][nt][2] + bb.x + rb.x;
            float v3 = acc[mt][nt][3] + bb.y + rb.y;
            acc[mt][nt][0] = v0; acc[mt][nt][1] = v1;
            acc[mt][nt][2] = v2; acc[mt][nt][3] = v3;
            *(float2*)(D + (size_t)r0 * 128 + col)       = make_float2(v0, v1);
            *(float2*)(D + (size_t)(r0 + 8) * 128 + col) = make_float2(v2, v3);
            s1[mt][0] += v0 + v1;        s2[mt][0] += v0 * v0 + v1 * v1;
            s1[mt][1] += v2 + v3;        s2[mt][1] += v2 * v2 + v3 * v3;
        }
    }
    #pragma unroll
    for (int o = 1; o <= 2; o <<= 1) {
        #pragma unroll
        for (int mt = 0; mt < 2; mt++) {
            #pragma unroll
            for (int h = 0; h < 2; h++) {
                s1[mt][h] += __shfl_xor_sync(0xffffffffu, s1[mt][h], o);
                s2[mt][h] += __shfl_xor_sync(0xffffffffu, s2[mt][h], o);
            }
        }
    }
    if ((lane & 3) == 0) {
        #pragma unroll
        for (int mt = 0; mt < 2; mt++)
            #pragma unroll
            for (int h = 0; h < 2; h++)
                red[wm * 32 + mt * 16 + h * 8 + lr][wn] =
                    make_float2(s1[mt][h], s2[mt][h]);
    }
    __syncthreads();

    #pragma unroll
    for (int mt = 0; mt < 2; mt++) {
        #pragma unroll
        for (int h = 0; h < 2; h++) {
            int rl = wm * 32 + mt * 16 + h * 8 + lr;
            float2 r0v = red[rl][0];
            float2 r1v = red[rl][1];
            float2 r2v = red[rl][2];
            float2 r3v = red[rl][3];
            float mu = (r0v.x + r1v.x + r2v.x + r3v.x) * (1.0f / 128.0f);
            float var = (r0v.y + r1v.y + r2v.y + r3v.y) * (1.0f / 128.0f) - mu * mu;
            float rs = rsqrtf(var + 1e-5f);
            __nv_bfloat16* op = ln_out + (size_t)(mBase + rl) * 128;
            #pragma unroll
            for (int nt = 0; nt < 4; nt++) {
                int col = wn * 32 + nt * 8 + lc;
                float2 gg = *(const float2*)(n2g + col);
                float2 bb = *(const float2*)(n2b + col);
                float v0 = acc[mt][nt][h * 2];
                float v1 = acc[mt][nt][h * 2 + 1];
                float l0 = (v0 - mu) * rs * gg.x + bb.x;
                float l1 = (v1 - mu) * rs * gg.y + bb.y;
                __nv_bfloat162 pr = __floats2bfloat162_rn(l0, l1);
                *(__nv_bfloat162*)(op + col) = pr;
            }
        }
    }
}

// ---------------------------------------------------------------------------
// Fused MLP v2 (unchanged): double-buffered weight chunks.
// ---------------------------------------------------------------------------
#define AOFF  0
#define HOFF  17408
#define W1OFF 26624
#define W2OFF 61440
#define W1SZ  17408          // 64 * 272
#define W2SZ  18432          // 128 * 144
#define MLP_SMEM 98304

__global__ __launch_bounds__(256, 2) void mlp_kernel(
    const __nv_bfloat16* __restrict__ Aln, const __nv_bfloat16* __restrict__ W1t,
    const __nv_bfloat16* __restrict__ W2t, float* __restrict__ out,
    const float* __restrict__ b1, const float* __restrict__ b2,
    const float* __restrict__ res)
{
    extern __shared__ __align__(16) char dsm[];
    uint32_t sbase = smem_u32(dsm);

    int tid = threadIdx.x;
    int warp = tid >> 5;
    int lane = tid & 31;
    int wm = warp >> 2;
    int wn = warp & 3;
    int mBase = blockIdx.y * 64;
    int lr = lane >> 2;
    int lc = (lane & 3) * 2;

    auto issueW = [&](int h) {
        int buf = h & 1;
        #pragma unroll
        for (int it = 0; it < 4; it++) {
            int idx = it * 256 + tid;
            int r = idx >> 4, c = idx & 15;
            cp16(sbase + W1OFF + buf * W1SZ + r * 272 + c * 16,
                 W1t + (size_t)(h * 64 + r) * 128 + c * 8);
        }
        #pragma unroll
        for (int it = 0; it < 4; it++) {
            int idx = it * 256 + tid;
            int r = idx >> 3, c = idx & 7;
            cp16(sbase + W2OFF + buf * W2SZ + r * 144 + c * 16,
                 W2t + (size_t)r * 512 + h * 64 + c * 8);
        }
    };

    #pragma unroll
    for (int it = 0; it < 4; it++) {
        int idx = it * 256 + tid;
        int r = idx >> 4, c = idx & 15;
        cp16(sbase + AOFF + r * 272 + c * 16,
             Aln + (size_t)(mBase + r) * 128 + c * 8);
    }
    issueW(0);
    CP_COMMIT();

    float acc2[2][4][4];
    #pragma unroll
    for (int i = 0; i < 2; i++)
        #pragma unroll
        for (int j = 0; j < 4; j++)
            #pragma unroll
            for (int q = 0; q < 4; q++) acc2[i][j][q] = 0.0f;

    for (int h = 0; h < 8; h++) {
        if (h + 1 < 8) {
            issueW(h + 1);
            CP_COMMIT();
            CP_WAIT1();
        } else {
            CP_WAIT0();
        }
        __syncthreads();

        uint32_t w1b = sbase + W1OFF + (h & 1) * W1SZ;
        uint32_t w2b = sbase + W2OFF + (h & 1) * W2SZ;

        float acc1[2][2][4];
        #pragma unroll
        for (int i = 0; i < 2; i++)
            #pragma unroll
            for (int j = 0; j < 2; j++)
                #pragma unroll
                for (int q = 0; q < 4; q++) acc1[i][j][q] = 0.0f;

        #pragma unroll
        for (int ks = 0; ks < 8; ks++) {
            uint32_t af[2][4];
            #pragma unroll
            for (int mt = 0; mt < 2; mt++) {
                int row = wm * 32 + mt * 16 + (lane & 15);
                int koff = ks * 16 + ((lane >> 4) << 3);
                ldsm_x4(af[mt][0], af[mt][1], af[mt][2], af[mt][3],
                        sbase + AOFF + row * 272 + koff * 2);
            }
            uint32_t bf1[4];
            {
                int row = wn * 16 + (((lane >> 4) & 1) << 3) + (lane & 7);
                int koff = ks * 16 + (((lane >> 3) & 1) << 3);
                ldsm_x4(bf1[0], bf1[1], bf1[2], bf1[3], w1b + row * 272 + koff * 2);
            }
            #pragma unroll
            for (int mt = 0; mt < 2; mt++)
                #pragma unroll
                for (int nt = 0; nt < 2; nt++)
                    mma_bf16(acc1[mt][nt], af[mt], bf1[nt * 2], bf1[nt * 2 + 1]);
        }

        #pragma unroll
        for (int mt = 0; mt < 2; mt++) {
            int row0 = wm * 32 + mt * 16 + lr;
            #pragma unroll
            for (int nt = 0; nt < 2; nt++) {
                int cc = wn * 16 + nt * 8 + lc;
                float2 bb = *(const float2*)(b1 + h * 64 + cc);
                float v0 = acc1[mt][nt][0] + bb.x;
                float v1 = acc1[mt][nt][1] + bb.y;
                float v2 = acc1[mt][nt][2] + bb.x;
                float v3 = acc1[mt][nt][3] + bb.y;
                v0 = 0.5f * v0 * (1.0f + erff(v0 * 0.70710678118654752f));
                v1 = 0.5f * v1 * (1.0f + erff(v1 * 0.70710678118654752f));
                v2 = 0.5f * v2 * (1.0f + erff(v2 * 0.70710678118654752f));
                v3 = 0.5f * v3 * (1.0f + erff(v3 * 0.70710678118654752f));
                __nv_bfloat162 pa = __floats2bfloat162_rn(v0, v1);
                __nv_bfloat162 pb = __floats2bfloat162_rn(v2, v3);
                *(__nv_bfloat162*)(dsm + HOFF + row0 * 144 + cc * 2) = pa;
                *(__nv_bfloat162*)(dsm + HOFF + (row0 + 8) * 144 + cc * 2) = pb;
            }
        }
        __syncthreads();

        #pragma unroll
        for (int ks = 0; ks < 4; ks++) {
            uint32_t af[2][4];
            #pragma unroll
            for (int mt = 0; mt < 2; mt++) {
                int row = wm * 32 + mt * 16 + (lane & 15);
                int koff = ks * 16 + ((lane >> 4) << 3);
                ldsm_x4(af[mt][0], af[mt][1], af[mt][2], af[mt][3],
                        sbase + HOFF + row * 144 + koff * 2);
            }
            uint32_t bf2[2][4];
            #pragma unroll
            for (int nt2 = 0; nt2 < 2; nt2++) {
                int row = wn * 32 + nt2 * 16 + (((lane >> 4) & 1) << 3) + (lane & 7);
                int koff = ks * 16 + (((lane >> 3) & 1) << 3);
                ldsm_x4(bf2[nt2][0], bf2[nt2][1], bf2[nt2][2], bf2[nt2][3],
                        w2b + row * 144 + koff * 2);
            }
            #pragma unroll
            for (int mt = 0; mt < 2; mt++)
                #pragma unroll
                for (int nt = 0; nt < 4; nt++)
                    mma_bf16(acc2[mt][nt], af[mt],
                             bf2[nt >> 1][(nt & 1) * 2], bf2[nt >> 1][(nt & 1) * 2 + 1]);
        }
        __syncthreads();
    }

    #pragma unroll
    for (int mt = 0; mt < 2; mt++) {
        int r0 = mBase + wm * 32 + mt * 16 + lr;
        #pragma unroll
        for (int nt = 0; nt < 4; nt++) {
            int col = wn * 32 + nt * 8 + lc;
            float2 bb = *(const float2*)(b2 + col);
            float2 ra = *(const float2*)(res + (size_t)r0 * 128 + col);
            float2 rb = *(const float2*)(res + (size_t)(r0 + 8) * 128 + col);
            *(float2*)(out + (size_t)r0 * 128 + col) =
                make_float2(acc2[mt][nt][0] + bb.x + ra.x,
                            acc2[mt][nt][1] + bb.y + ra.y);
            *(float2*)(out + (size_t)(r0 + 8) * 128 + col) =
                make_float2(acc2[mt][nt][2] + bb.x + rb.x,
                            acc2[mt][nt][3] + bb.y + rb.y);
        }
    }
}

// ---------------------------------------------------------------------------
// Flash-style HMMA window attention + fused LEPE, templated on branch (R12).
// One block per (branch, window, head): 3584 blocks, 224 threads (7 warps).
// ---------------------------------------------------------------------------
#define AROW 80   // bytes per smem row in attention tiles (40 bf16)

template<int BRANCH>
__device__ __forceinline__ void attn_body(
    const __nv_bfloat16* __restrict__ qkv,
    const float* __restrict__ cw0, const float* __restrict__ cb0,
    const float* __restrict__ cw1, const float* __restrict__ cb1,
    __nv_bfloat16* __restrict__ outp,
    char* smQc, char* smKc, char* smVc, float* cwS, float* cbS,
    int rem)
{
    constexpr int Hsp = BRANCH ? 2 : RESO_;
    constexpr int Wsp = BRANCH ? RESO_ : 2;

    int win = rem >> 1;
    int head = rem & 1;
    int b = win / NWIN_;
    int slot = win - b * NWIN_;
    int cb = BRANCH * 64 + head * 32;
    int tid = threadIdx.x;
    int warp = tid >> 5;
    int lane = tid & 31;
    const float kscale = 0.17677669529663687f * 1.4426950408889634f;

    uint32_t sQ = smem_u32(smQc);
    uint32_t sK = smem_u32(smKc);
    uint32_t sV = smem_u32(smVc);

    {
        const float* cw = (BRANCH ? cw1 : cw0) + head * 32 * 9;
        const float* cbp = (BRANCH ? cb1 : cb0) + head * 32;
        for (int i = tid; i < 288; i += 224) {
            int d = i / 9, wi = i - d * 9;
            cwS[wi * 32 + d] = cw[i];
        }
        if (tid < 32) cbS[tid] = cbp[tid];
    }

    #pragma unroll
    for (int tile = 0; tile < 3; tile++) {
        char* dst = (tile == 0 ? smQc : tile == 1 ? smKc : smVc);
        #pragma unroll
        for (int it = 0; it < 2; it++) {
            int idx = it * 224 + tid;
            int t = idx >> 2;
            int f = idx & 3;
            int pix;
            if (BRANCH == 0) {
                pix = (t >> 1) * RESO_ + slot * 2 + (t & 1);
            } else {
                int hs = (t >= RESO_) ? 1 : 0;
                pix = (slot * 2 + hs) * RESO_ + (t - hs * RESO_);
            }
            size_t ro = ((size_t)(b * L_ + pix)) * 384 + cb + tile * 128 + f * 8;
            *(uint4*)(dst + t * AROW + f * 16) = *(const uint4*)(qkv + ro);
        }
    }
    __syncthreads();

    uint32_t af[2][4];
    #pragma unroll
    for (int kt = 0; kt < 2; kt++) {
        int row = warp * 16 + (lane & 15);
        int koff = kt * 16 + ((lane >> 4) << 3);
        ldsm_x4(af[kt][0], af[kt][1], af[kt][2], af[kt][3],
                sQ + row * AROW + koff * 2);
    }

    float s[14][4];
    #pragma unroll
    for (int nt = 0; nt < 14; nt++) {
        s[nt][0] = s[nt][1] = s[nt][2] = s[nt][3] = 0.0f;
        uint32_t kb[4];
        ldsm_x4(kb[0], kb[1], kb[2], kb[3],
                sK + (nt * 8 + (lane & 7)) * AROW + (lane >> 3) * 16);
        mma_bf16(s[nt], af[0], kb[0], kb[1]);
        mma_bf16(s[nt], af[1], kb[2], kb[3]);
    }

    float m0 = -1e30f, m1 = -1e30f;
    #pragma unroll
    for (int nt = 0; nt < 14; nt++) {
        m0 = fmaxf(m0, fmaxf(s[nt][0], s[nt][1]));
        m1 = fmaxf(m1, fmaxf(s[nt][2], s[nt][3]));
    }
    #pragma unroll
    for (int o = 1; o <= 2; o <<= 1) {
        m0 = fmaxf(m0, __shfl_xor_sync(0xffffffffu, m0, o));
        m1 = fmaxf(m1, __shfl_xor_sync(0xffffffffu, m1, o));
    }
    float m0k = m0 * kscale;
    float m1k = m1 * kscale;
    float sum0 = 0.0f, sum1 = 0.0f;
    uint32_t p01[14], p23[14];
    #pragma unroll
    for (int nt = 0; nt < 14; nt++) {
        float e0 = exp2f(fmaf(s[nt][0], kscale, -m0k));
        float e1 = exp2f(fmaf(s[nt][1], kscale, -m0k));
        float e2 = exp2f(fmaf(s[nt][2], kscale, -m1k));
        float e3 = exp2f(fmaf(s[nt][3], kscale, -m1k));
        sum0 += e0 + e1;
        sum1 += e2 + e3;
        __nv_bfloat162 pa = __floats2bfloat162_rn(e0, e1);
        __nv_bfloat162 pb = __floats2bfloat162_rn(e2, e3);
        p01[nt] = *reinterpret_cast<uint32_t*>(&pa);
        p23[nt] = *reinterpret_cast<uint32_t*>(&pb);
    }
    #pragma unroll
    for (int o = 1; o <= 2; o <<= 1) {
        sum0 += __shfl_xor_sync(0xffffffffu, sum0, o);
        sum1 += __shfl_xor_sync(0xffffffffu, sum1, o);
    }
    float inv0 = 1.0f / sum0;
    float inv1 = 1.0f / sum1;

    float oacc[4][4];
    #pragma unroll
    for (int nt = 0; nt < 4; nt++)
        oacc[nt][0] = oacc[nt][1] = oacc[nt][2] = oacc[nt][3] = 0.0f;

    #pragma unroll
    for (int kt = 0; kt < 7; kt++) {
        uint32_t pa[4] = {p01[2 * kt], p23[2 * kt], p01[2 * kt + 1], p23[2 * kt + 1]};
        uint32_t vb[4], vb2[4];
        uint32_t vaddr = sV + (kt * 16 + (lane & 15)) * AROW + (lane >> 4) * 16;
        ldsm_x4_t(vb[0],  vb[1],  vb[2],  vb[3],  vaddr);
        ldsm_x4_t(vb2[0], vb2[1], vb2[2], vb2[3], vaddr + 32);
        mma_bf16(oacc[0], pa, vb[0],  vb[1]);
        mma_bf16(oacc[1], pa, vb[2],  vb[3]);
        mma_bf16(oacc[2], pa, vb2[0], vb2[1]);
        mma_bf16(oacc[3], pa, vb2[2], vb2[3]);
    }

    const __nv_bfloat16* Vbf = (const __nv_bfloat16*)smVc;
    int lr = lane >> 2;
    int lc = (lane & 3) * 2;

    #pragma unroll
    for (int half = 0; half < 2; half++) {
        int tok = warp * 16 + lr + half * 8;
        float inv = half ? inv1 : inv0;
        int hs, ws;
        if (BRANCH == 0) { hs = tok >> 1; ws = tok & 1; }
        else             { hs = (tok >= RESO_) ? 1 : 0; ws = tok - hs * RESO_; }

        float l[8];
        #pragma unroll
        for (int nt = 0; nt < 4; nt++) {
            l[nt * 2]     = cbS[nt * 8 + lc];
            l[nt * 2 + 1] = cbS[nt * 8 + lc + 1];
        }
        #pragma unroll
        for (int wi = 0; wi < 9; wi++) {
            int dy = wi / 3 - 1, dx = wi - (wi / 3) * 3 - 1;
            int y = hs + dy, x = ws + dx;
            if (y >= 0 && y < Hsp && x >= 0 && x < Wsp) {
                const __nv_bfloat16* vp = Vbf + (y * Wsp + x) * 40;
                const float* wp = cwS + wi * 32;
                #pragma unroll
                for (int nt = 0; nt < 4; nt++) {
                    int d0 = nt * 8 + lc;
                    float2 vv = __bfloat1622float2(*(const __nv_bfloat162*)(vp + d0));
                    l[nt * 2]     += wp[d0]     * vv.x;
                    l[nt * 2 + 1] += wp[d0 + 1] * vv.y;
                }
            }
        }

        int pix;
        if (BRANCH == 0) pix = hs * RESO_ + slot * 2 + ws;
        else             pix = (slot * 2 + hs) * RESO_ + ws;
        __nv_bfloat16* op = outp + ((size_t)(b * L_ + pix)) * C_ + cb;

        #pragma unroll
        for (int nt = 0; nt < 4; nt++) {
            float v0 = oacc[nt][half * 2]     * inv + l[nt * 2];
            float v1 = oacc[nt][half * 2 + 1] * inv + l[nt * 2 + 1];
            __nv_bfloat162 pr = __floats2bfloat162_rn(v0, v1);
            *(__nv_bfloat162*)(op + nt * 8 + lc) = pr;
        }
    }
}

__global__ __launch_bounds__(224, 4) void attn_kernel(
    const __nv_bfloat16* __restrict__ qkv,
    const float* __restrict__ cw0, const float* __restrict__ cb0,
    const float* __restrict__ cw1, const float* __restrict__ cb1,
    __nv_bfloat16* __restrict__ outp)
{
    __shared__ __align__(16) char smQ[TOK_ * AROW];
    __shared__ __align__(16) char smK[TOK_ * AROW];
    __shared__ __align__(16) char smV[TOK_ * AROW];
    __shared__ float cwS[288];
    __shared__ float cbS[32];

    int bid = blockIdx.x;
    if (bid < 1792)
        attn_body<0>(qkv, cw0, cb0, cw1, cb1, outp, smQ, smK, smV, cwS, cbS, bid);
    else
        attn_body<1>(qkv, cw0, cb0, cw1, cb1, outp, smQ, smK, smV, cwS, cbS, bid - 1792);
}

// ---------------------------------------------------------------------------
extern "C" void kernel_launch(void* const* d_in, const int* in_sizes, int n_in,
                              void* d_out, int out_size)
{
    const float* x       = (const float*)d_in[0];
    const float* n1g     = (const float*)d_in[1];
    const float* n1b     = (const float*)d_in[2];
    const float* qkv_w   = (const float*)d_in[3];
    const float* proj_w  = (const float*)d_in[4];
    const float* proj_b  = (const float*)d_in[5];
    const float* conv_w0 = (const float*)d_in[6];
    const float* conv_b0 = (const float*)d_in[7];
    const float* conv_w1 = (const float*)d_in[8];
    const float* conv_b1 = (const float*)d_in[9];
    const float* n2g     = (const float*)d_in[10];
    const float* n2b     = (const float*)d_in[11];
    const float* fc1_w   = (const float*)d_in[12];
    const float* fc1_b   = (const float*)d_in[13];
    const float* fc2_w   = (const float*)d_in[14];
    const float* fc2_b   = (const float*)d_in[15];
    float* out = (float*)d_out;

    __nv_bfloat16 *ln, *qkvb, *attn, *wts;
    float *xr;
    cudaGetSymbolAddress((void**)&ln,   g_ln);
    cudaGetSymbolAddress((void**)&qkvb, g_qkv);
    cudaGetSymbolAddress((void**)&attn, g_attn);
    cudaGetSymbolAddress((void**)&xr,   g_x);
    cudaGetSymbolAddress((void**)&wts,  g_w);

    __nv_bfloat16* w_qkv = wts;                 // [384,128]
    __nv_bfloat16* w_prj = wts + 49152;         // [128,128]
    __nv_bfloat16* w_fc1 = wts + 65536;         // [512,128]
    __nv_bfloat16* w_fc2 = wts + 131072;        // [128,512]

    cudaFuncSetAttribute(mlp_kernel,
                         cudaFuncAttributeMaxDynamicSharedMemorySize, MLP_SMEM);

    // 1. LN1 -> bf16 (+ folded weight convert in first 768 blocks)
    ln_conv_kernel<<<M_ / 8, 256>>>(x, n1g, n1b, ln,
                                    qkv_w, proj_w, fc1_w, fc2_w, wts);
    // 2. QKV GEMM -> bf16
    mma_gemm_kernel<<<dim3(3, M_ / 128), 256>>>(ln, w_qkv, qkvb, 384, 128,
                                                nullptr, nullptr, 0);
    // 3. Flash-style HMMA window attention + LEPE -> bf16
    attn_kernel<<<3584, 224>>>(qkvb, conv_w0, conv_b0, conv_w1, conv_b1, attn);
    // 4. proj GEMM + bias + residual(x) -> fp32 xr, fused LN2 -> bf16 ln
    proj_ln_kernel<<<dim3(1, M_ / 64), 256>>>(attn, w_prj, xr,
                                              proj_b, x, n2g, n2b, ln);
    // 5. fused MLP (double-buffered): GELU(ln@W1+b1)@W2 + b2 + xr -> fp32 out
    mlp_kernel<<<dim3(1, M_ / 64), 256, MLP_SMEM>>>(ln, w_fc1, w_fc2, out,
                                                    fc1_b, fc2_b, xr);
}

// round 17
// speedup vs baseline: 1.0436x; 1.0206x over previous
#include <cuda_runtime.h>
#include <cuda_bf16.h>
#include <math.h>
#include <stdint.h>

// Problem constants
#define BATCH_ 32
#define RESO_ 56
#define L_ (RESO_ * RESO_)          // 3136
#define C_ 128
#define M_ (BATCH_ * L_)            // 100352 rows
#define HID_ 512
#define TOK_ 112                    // window tokens (56*2)
#define NWIN_ 28                    // windows per batch per branch

// Scratch buffers (device globals: allocation-free)
__device__ __nv_bfloat16 g_ln  [(size_t)M_ * C_];
__device__ __nv_bfloat16 g_qkv [(size_t)M_ * 3 * C_];
__device__ __nv_bfloat16 g_attn[(size_t)M_ * C_];
__device__ float         g_x   [(size_t)M_ * C_];
__device__ __nv_bfloat16 g_w   [196608];   // transposed bf16 weights

// ---------------------------------------------------------------------------
// PTX helpers (baseline PTX, portable to compute_103)
// ---------------------------------------------------------------------------
__device__ __forceinline__ uint32_t smem_u32(const void* p) {
    uint32_t a;
    asm("{ .reg .u64 t; cvta.to.shared.u64 t, %1; cvt.u32.u64 %0, t; }" : "=r"(a) : "l"(p));
    return a;
}
__device__ __forceinline__ void cp16(uint32_t dst, const void* src) {
    asm volatile("cp.async.cg.shared.global [%0], [%1], 16;" :: "r"(dst), "l"(src));
}
#define CP_COMMIT() asm volatile("cp.async.commit_group;" ::: "memory")
#define CP_WAIT3()  asm volatile("cp.async.wait_group 3;" ::: "memory")
#define CP_WAIT2()  asm volatile("cp.async.wait_group 2;" ::: "memory")
#define CP_WAIT1()  asm volatile("cp.async.wait_group 1;" ::: "memory")
#define CP_WAIT0()  asm volatile("cp.async.wait_group 0;" ::: "memory")

__device__ __forceinline__ void ldsm_x4(uint32_t& r0, uint32_t& r1,
                                        uint32_t& r2, uint32_t& r3, uint32_t addr) {
    asm volatile("ldmatrix.sync.aligned.m8n8.x4.shared.b16 {%0,%1,%2,%3}, [%4];"
                 : "=r"(r0), "=r"(r1), "=r"(r2), "=r"(r3) : "r"(addr));
}
__device__ __forceinline__ void ldsm_x4_t(uint32_t& r0, uint32_t& r1,
                                          uint32_t& r2, uint32_t& r3, uint32_t addr) {
    asm volatile("ldmatrix.sync.aligned.m8n8.x4.trans.shared.b16 {%0,%1,%2,%3}, [%4];"
                 : "=r"(r0), "=r"(r1), "=r"(r2), "=r"(r3) : "r"(addr));
}
__device__ __forceinline__ void mma_bf16(float* c, const uint32_t* a,
                                         uint32_t b0, uint32_t b1) {
    asm volatile("mma.sync.aligned.m16n8k16.row.col.f32.bf16.bf16.f32 "
                 "{%0,%1,%2,%3}, {%4,%5,%6,%7}, {%8,%9}, {%0,%1,%2,%3};"
                 : "+f"(c[0]), "+f"(c[1]), "+f"(c[2]), "+f"(c[3])
                 : "r"(a[0]), "r"(a[1]), "r"(a[2]), "r"(a[3]), "r"(b0), "r"(b1));
}

// ---------------------------------------------------------------------------
// LayerNorm (one warp per row) + folded weight convert/transpose in blocks<768.
// ---------------------------------------------------------------------------
__global__ __launch_bounds__(256) void ln_conv_kernel(
    const float* __restrict__ in, const float* __restrict__ g,
    const float* __restrict__ b, __nv_bfloat16* __restrict__ out,
    const float* __restrict__ qkv_w, const float* __restrict__ proj_w,
    const float* __restrict__ fc1_w, const float* __restrict__ fc2_w,
    __nv_bfloat16* __restrict__ wout)
{
    if (blockIdx.x < 768) {
        int i = blockIdx.x * 256 + threadIdx.x;
        float v;
        if (i < 49152) {
            int n = i >> 7, k = i & 127;
            v = qkv_w[(size_t)k * 384 + n];
        } else if (i < 65536) {
            int j = i - 49152;    int n = j >> 7, k = j & 127;
            v = proj_w[(size_t)k * 128 + n];
        } else if (i < 131072) {
            int j = i - 65536;    int n = j >> 7, k = j & 127;
            v = fc1_w[(size_t)k * 512 + n];
        } else {
            int j = i - 131072;   int n = j >> 9, k = j & 511;
            v = fc2_w[(size_t)k * 128 + n];
        }
        wout[i] = __float2bfloat16(v);
    }

    int warp = (blockIdx.x * blockDim.x + threadIdx.x) >> 5;
    int lane = threadIdx.x & 31;
    if (warp >= M_) return;
    float4 v = ((const float4*)(in + (size_t)warp * C_))[lane];
    float s = v.x + v.y + v.z + v.w;
    #pragma unroll
    for (int o = 16; o; o >>= 1) s += __shfl_xor_sync(0xffffffffu, s, o);
    float mu = s * (1.0f / C_);
    float dx = v.x - mu, dy = v.y - mu, dz = v.z - mu, dw = v.w - mu;
    float q = dx*dx + dy*dy + dz*dz + dw*dw;
    #pragma unroll
    for (int o = 16; o; o >>= 1) q += __shfl_xor_sync(0xffffffffu, q, o);
    float rs = rsqrtf(q * (1.0f / C_) + 1e-5f);
    float4 gg = ((const float4*)g)[lane];
    float4 bb = ((const float4*)b)[lane];
    __nv_bfloat162 p0 = __floats2bfloat162_rn(dx * rs * gg.x + bb.x, dy * rs * gg.y + bb.y);
    __nv_bfloat162 p1 = __floats2bfloat162_rn(dz * rs * gg.z + bb.z, dw * rs * gg.w + bb.w);
    uint2 u;
    u.x = *reinterpret_cast<uint32_t*>(&p0);
    u.y = *reinterpret_cast<uint32_t*>(&p1);
    ((uint2*)(out + (size_t)warp * C_))[lane] = u;
}

// ---------------------------------------------------------------------------
// QKV GEMM: 128x128 tile, K=128 in 4 FULLY-PREFETCHED chunk buffers.
// All loads issued up front (4 cp.async groups, no buffer reuse);
// per chunk: wait_group(3-c) -> one sync -> compute. 4 syncs total.
// Dyn smem 81920 B -> 2 blocks/SM.
// ---------------------------------------------------------------------------
#define ROWB 80        // bytes per padded smem row (40 bf16)
#define QKV_CHUNK (128 * ROWB)          // 10240 B per matrix chunk
#define QKV_SMEM  (8 * QKV_CHUNK)       // 4 chunks x (A+B) = 81920 B

__global__ __launch_bounds__(256) void qkv_gemm_kernel(
    const __nv_bfloat16* __restrict__ A, const __nv_bfloat16* __restrict__ Bt,
    __nv_bfloat16* __restrict__ D)
{
    extern __shared__ __align__(16) char qsm[];
    uint32_t sbase = smem_u32(qsm);

    int tid = threadIdx.x;
    int warp = tid >> 5;
    int lane = tid & 31;
    int wm = warp >> 1;
    int wn = warp & 1;
    int mBase = blockIdx.y * 128;
    int nBase = blockIdx.x * 128;

    // Prefetch all 4 chunks (A then B per chunk), one commit group each.
    #pragma unroll
    for (int c = 0; c < 4; c++) {
        #pragma unroll
        for (int it = 0; it < 2; it++) {
            int idx = it * 256 + tid;
            int r = idx >> 2, cc = idx & 3;
            uint32_t off = (uint32_t)(r * ROWB + cc * 16);
            cp16(sbase + (2 * c) * QKV_CHUNK + off,
                 A  + (size_t)(mBase + r) * 128 + c * 32 + cc * 8);
            cp16(sbase + (2 * c + 1) * QKV_CHUNK + off,
                 Bt + (size_t)(nBase + r) * 128 + c * 32 + cc * 8);
        }
        CP_COMMIT();
    }

    float acc[2][8][4];
    #pragma unroll
    for (int i = 0; i < 2; i++)
        #pragma unroll
        for (int j = 0; j < 8; j++)
            #pragma unroll
            for (int q = 0; q < 4; q++) acc[i][j][q] = 0.0f;

    auto compute = [&](int c) {
        uint32_t aB = sbase + (2 * c) * QKV_CHUNK;
        uint32_t bB = sbase + (2 * c + 1) * QKV_CHUNK;
        #pragma unroll
        for (int ks = 0; ks < 2; ks++) {
            uint32_t af[2][4];
            #pragma unroll
            for (int mt = 0; mt < 2; mt++) {
                int row = wm * 32 + mt * 16 + (lane & 15);
                int koff = ks * 16 + ((lane >> 4) << 3);
                ldsm_x4(af[mt][0], af[mt][1], af[mt][2], af[mt][3],
                        aB + row * ROWB + koff * 2);
            }
            uint32_t bf[4][4];
            #pragma unroll
            for (int nt2 = 0; nt2 < 4; nt2++) {
                int row = wn * 64 + nt2 * 16 + (((lane >> 4) & 1) << 3) + (lane & 7);
                int koff = ks * 16 + (((lane >> 3) & 1) << 3);
                ldsm_x4(bf[nt2][0], bf[nt2][1], bf[nt2][2], bf[nt2][3],
                        bB + row * ROWB + koff * 2);
            }
            #pragma unroll
            for (int mt = 0; mt < 2; mt++)
                #pragma unroll
                for (int nt = 0; nt < 8; nt++)
                    mma_bf16(acc[mt][nt], af[mt],
                             bf[nt >> 1][(nt & 1) * 2], bf[nt >> 1][(nt & 1) * 2 + 1]);
        }
    };

    CP_WAIT3(); __syncthreads(); compute(0);
    CP_WAIT2(); __syncthreads(); compute(1);
    CP_WAIT1(); __syncthreads(); compute(2);
    CP_WAIT0(); __syncthreads(); compute(3);

    int lr = lane >> 2;
    int lc = (lane & 3) * 2;
    #pragma unroll
    for (int mt = 0; mt < 2; mt++) {
        int r0 = mBase + wm * 32 + mt * 16 + lr;
        #pragma unroll
        for (int nt = 0; nt < 8; nt++) {
            int col = nBase + wn * 64 + nt * 8 + lc;
            __nv_bfloat162 pa = __floats2bfloat162_rn(acc[mt][nt][0], acc[mt][nt][1]);
            __nv_bfloat162 pb = __floats2bfloat162_rn(acc[mt][nt][2], acc[mt][nt][3]);
            *(__nv_bfloat162*)(D + (size_t)r0 * 384 + col)       = pa;
            *(__nv_bfloat162*)(D + (size_t)(r0 + 8) * 384 + col) = pb;
        }
    }
}

// ---------------------------------------------------------------------------
// proj + LN2 fused, v3 (R12): M-tile 64, 8 warps (2m x 4n), 32-reg acc
// kept live through the LN output phase.
// ---------------------------------------------------------------------------
__global__ __launch_bounds__(256, 3) void proj_ln_kernel(
    const __nv_bfloat16* __restrict__ A, const __nv_bfloat16* __restrict__ Bt,
    float* __restrict__ D,
    const float* __restrict__ bias, const float* __restrict__ res,
    const float* __restrict__ n2g, const float* __restrict__ n2b,
    __nv_bfloat16* __restrict__ ln_out)
{
    __shared__ __align__(16) char smA[64 * 272];
    __shared__ __align__(16) char smB[128 * 272];
    __shared__ float2 red[64][4];

    int tid = threadIdx.x;
    int warp = tid >> 5;
    int lane = tid & 31;
    int wm = warp >> 2;
    int wn = warp & 3;
    int mBase = blockIdx.y * 64;

    uint32_t sA = smem_u32(smA);
    uint32_t sB = smem_u32(smB);

    #pragma unroll
    for (int kh = 0; kh < 2; kh++) {
        #pragma unroll
        for (int it = 0; it < 2; it++) {   // A half: 512 cp16
            int idx = it * 256 + tid;
            int r = idx >> 3, c = idx & 7;
            cp16(sA + r * 272 + kh * 128 + c * 16,
                 A + (size_t)(mBase + r) * 128 + kh * 64 + c * 8);
        }
        #pragma unroll
        for (int it = 0; it < 4; it++) {   // B half: 1024 cp16
            int idx = it * 256 + tid;
            int r = idx >> 3, c = idx & 7;
            cp16(sB + r * 272 + kh * 128 + c * 16,
                 Bt + (size_t)r * 128 + kh * 64 + c * 8);
        }
        CP_COMMIT();
    }

    float acc[2][4][4];
    #pragma unroll
    for (int i = 0; i < 2; i++)
        #pragma unroll
        for (int j = 0; j < 4; j++)
            #pragma unroll
            for (int q = 0; q < 4; q++) acc[i][j][q] = 0.0f;

    #pragma unroll
    for (int kh = 0; kh < 2; kh++) {
        if (kh == 0) CP_WAIT1(); else CP_WAIT0();
        __syncthreads();
        #pragma unroll
        for (int ki = 0; ki < 4; ki++) {
            int ks = kh * 4 + ki;
            uint32_t af[2][4];
            #pragma unroll
            for (int mt = 0; mt < 2; mt++) {
                int row = wm * 32 + mt * 16 + (lane & 15);
                int koff = ks * 16 + ((lane >> 4) << 3);
                ldsm_x4(af[mt][0], af[mt][1], af[mt][2], af[mt][3],
                        sA + row * 272 + koff * 2);
            }
            uint32_t bf[2][4];
            #pragma unroll
            for (int nt2 = 0; nt2 < 2; nt2++) {
                int row = wn * 32 + nt2 * 16 + (((lane >> 4) & 1) << 3) + (lane & 7);
                int koff = ks * 16 + (((lane >> 3) & 1) << 3);
                ldsm_x4(bf[nt2][0], bf[nt2][1], bf[nt2][2], bf[nt2][3],
                        sB + row * 272 + koff * 2);
            }
            #pragma unroll
            for (int mt = 0; mt < 2; mt++)
                #pragma unroll
                for (int nt = 0; nt < 4; nt++)
                    mma_bf16(acc[mt][nt], af[mt],
                             bf[nt >> 1][(nt & 1) * 2], bf[nt >> 1][(nt & 1) * 2 + 1]);
        }
    }

    int lr = lane >> 2;
    int lc = (lane & 3) * 2;

    float s1[2][2], s2[2][2];
    #pragma unroll
    for (int mt = 0; mt < 2; mt++)
        s1[mt][0] = s1[mt][1] = s2[mt][0] = s2[mt][1] = 0.0f;
    #pragma unroll
    for (int mt = 0; mt < 2; mt++) {
        int r0 = mBase + wm * 32 + mt * 16 + lr;
        #pragma unroll
        for (int nt = 0; nt < 4; nt++) {
            int col = wn * 32 + nt * 8 + lc;
            float2 bb = *(const float2*)(bias + col);
            float2 ra = *(const float2*)(res + (size_t)r0 * 128 + col);
            float2 rb = *(const float2*)(res + (size_t)(r0 + 8) * 128 + col);
            float v0 = acc[mt][nt][0] + bb.x + ra.x;
            float v1 = acc[mt][nt][1] + bb.y + ra.y;
            float v2 = acc[mt][nt][2] + bb.x + rb.x;
            float v3 = acc[mt][nt][3] + bb.y + rb.y;
            acc[mt][nt][0] = v0; acc[mt][nt][1] = v1;
            acc[mt][nt][2] = v2; acc[mt][nt][3] = v3;
            *(float2*)(D + (size_t)r0 * 128 + col)       = make_float2(v0, v1);
            *(float2*)(D + (size_t)(r0 + 8) * 128 + col) = make_float2(v2, v3);
            s1[mt][0] += v0 + v1;        s2[mt][0] += v0 * v0 + v1 * v1;
            s1[mt][1] += v2 + v3;        s2[mt][1] += v2 * v2 + v3 * v3;
        }
    }
    #pragma unroll
    for (int o = 1; o <= 2; o <<= 1) {
        #pragma unroll
        for (int mt = 0; mt < 2; mt++) {
            #pragma unroll
            for (int h = 0; h < 2; h++) {
                s1[mt][h] += __shfl_xor_sync(0xffffffffu, s1[mt][h], o);
                s2[mt][h] += __shfl_xor_sync(0xffffffffu, s2[mt][h], o);
            }
        }
    }
    if ((lane & 3) == 0) {
        #pragma unroll
        for (int mt = 0; mt < 2; mt++)
            #pragma unroll
            for (int h = 0; h < 2; h++)
                red[wm * 32 + mt * 16 + h * 8 + lr][wn] =
                    make_float2(s1[mt][h], s2[mt][h]);
    }
    __syncthreads();

    #pragma unroll
    for (int mt = 0; mt < 2; mt++) {
        #pragma unroll
        for (int h = 0; h < 2; h++) {
            int rl = wm * 32 + mt * 16 + h * 8 + lr;
            float2 r0v = red[rl][0];
            float2 r1v = red[rl][1];
            float2 r2v = red[rl][2];
            float2 r3v = red[rl][3];
            float mu = (r0v.x + r1v.x + r2v.x + r3v.x) * (1.0f / 128.0f);
            float var = (r0v.y + r1v.y + r2v.y + r3v.y) * (1.0f / 128.0f) - mu * mu;
            float rs = rsqrtf(var + 1e-5f);
            __nv_bfloat16* op = ln_out + (size_t)(mBase + rl) * 128;
            #pragma unroll
            for (int nt = 0; nt < 4; nt++) {
                int col = wn * 32 + nt * 8 + lc;
                float2 gg = *(const float2*)(n2g + col);
                float2 bb = *(const float2*)(n2b + col);
                float v0 = acc[mt][nt][h * 2];
                float v1 = acc[mt][nt][h * 2 + 1];
                float l0 = (v0 - mu) * rs * gg.x + bb.x;
                float l1 = (v1 - mu) * rs * gg.y + bb.y;
                __nv_bfloat162 pr = __floats2bfloat162_rn(l0, l1);
                *(__nv_bfloat162*)(op + col) = pr;
            }
        }
    }
}

// ---------------------------------------------------------------------------
// Fused MLP v2 (unchanged): double-buffered weight chunks.
// ---------------------------------------------------------------------------
#define AOFF  0
#define HOFF  17408
#define W1OFF 26624
#define W2OFF 61440
#define W1SZ  17408          // 64 * 272
#define W2SZ  18432          // 128 * 144
#define MLP_SMEM 98304

__global__ __launch_bounds__(256, 2) void mlp_kernel(
    const __nv_bfloat16* __restrict__ Aln, const __nv_bfloat16* __restrict__ W1t,
    const __nv_bfloat16* __restrict__ W2t, float* __restrict__ out,
    const float* __restrict__ b1, const float* __restrict__ b2,
    const float* __restrict__ res)
{
    extern __shared__ __align__(16) char dsm[];
    uint32_t sbase = smem_u32(dsm);

    int tid = threadIdx.x;
    int warp = tid >> 5;
    int lane = tid & 31;
    int wm = warp >> 2;
    int wn = warp & 3;
    int mBase = blockIdx.y * 64;
    int lr = lane >> 2;
    int lc = (lane & 3) * 2;

    auto issueW = [&](int h) {
        int buf = h & 1;
        #pragma unroll
        for (int it = 0; it < 4; it++) {
            int idx = it * 256 + tid;
            int r = idx >> 4, c = idx & 15;
            cp16(sbase + W1OFF + buf * W1SZ + r * 272 + c * 16,
                 W1t + (size_t)(h * 64 + r) * 128 + c * 8);
        }
        #pragma unroll
        for (int it = 0; it < 4; it++) {
            int idx = it * 256 + tid;
            int r = idx >> 3, c = idx & 7;
            cp16(sbase + W2OFF + buf * W2SZ + r * 144 + c * 16,
                 W2t + (size_t)r * 512 + h * 64 + c * 8);
        }
    };

    #pragma unroll
    for (int it = 0; it < 4; it++) {
        int idx = it * 256 + tid;
        int r = idx >> 4, c = idx & 15;
        cp16(sbase + AOFF + r * 272 + c * 16,
             Aln + (size_t)(mBase + r) * 128 + c * 8);
    }
    issueW(0);
    CP_COMMIT();

    float acc2[2][4][4];
    #pragma unroll
    for (int i = 0; i < 2; i++)
        #pragma unroll
        for (int j = 0; j < 4; j++)
            #pragma unroll
            for (int q = 0; q < 4; q++) acc2[i][j][q] = 0.0f;

    for (int h = 0; h < 8; h++) {
        if (h + 1 < 8) {
            issueW(h + 1);
            CP_COMMIT();
            CP_WAIT1();
        } else {
            CP_WAIT0();
        }
        __syncthreads();

        uint32_t w1b = sbase + W1OFF + (h & 1) * W1SZ;
        uint32_t w2b = sbase + W2OFF + (h & 1) * W2SZ;

        float acc1[2][2][4];
        #pragma unroll
        for (int i = 0; i < 2; i++)
            #pragma unroll
            for (int j = 0; j < 2; j++)
                #pragma unroll
                for (int q = 0; q < 4; q++) acc1[i][j][q] = 0.0f;

        #pragma unroll
        for (int ks = 0; ks < 8; ks++) {
            uint32_t af[2][4];
            #pragma unroll
            for (int mt = 0; mt < 2; mt++) {
                int row = wm * 32 + mt * 16 + (lane & 15);
                int koff = ks * 16 + ((lane >> 4) << 3);
                ldsm_x4(af[mt][0], af[mt][1], af[mt][2], af[mt][3],
                        sbase + AOFF + row * 272 + koff * 2);
            }
            uint32_t bf1[4];
            {
                int row = wn * 16 + (((lane >> 4) & 1) << 3) + (lane & 7);
                int koff = ks * 16 + (((lane >> 3) & 1) << 3);
                ldsm_x4(bf1[0], bf1[1], bf1[2], bf1[3], w1b + row * 272 + koff * 2);
            }
            #pragma unroll
            for (int mt = 0; mt < 2; mt++)
                #pragma unroll
                for (int nt = 0; nt < 2; nt++)
                    mma_bf16(acc1[mt][nt], af[mt], bf1[nt * 2], bf1[nt * 2 + 1]);
        }

        #pragma unroll
        for (int mt = 0; mt < 2; mt++) {
            int row0 = wm * 32 + mt * 16 + lr;
            #pragma unroll
            for (int nt = 0; nt < 2; nt++) {
                int cc = wn * 16 + nt * 8 + lc;
                float2 bb = *(const float2*)(b1 + h * 64 + cc);
                float v0 = acc1[mt][nt][0] + bb.x;
                float v1 = acc1[mt][nt][1] + bb.y;
                float v2 = acc1[mt][nt][2] + bb.x;
                float v3 = acc1[mt][nt][3] + bb.y;
                v0 = 0.5f * v0 * (1.0f + erff(v0 * 0.70710678118654752f));
                v1 = 0.5f * v1 * (1.0f + erff(v1 * 0.70710678118654752f));
                v2 = 0.5f * v2 * (1.0f + erff(v2 * 0.70710678118654752f));
                v3 = 0.5f * v3 * (1.0f + erff(v3 * 0.70710678118654752f));
                __nv_bfloat162 pa = __floats2bfloat162_rn(v0, v1);
                __nv_bfloat162 pb = __floats2bfloat162_rn(v2, v3);
                *(__nv_bfloat162*)(dsm + HOFF + row0 * 144 + cc * 2) = pa;
                *(__nv_bfloat162*)(dsm + HOFF + (row0 + 8) * 144 + cc * 2) = pb;
            }
        }
        __syncthreads();

        #pragma unroll
        for (int ks = 0; ks < 4; ks++) {
            uint32_t af[2][4];
            #pragma unroll
            for (int mt = 0; mt < 2; mt++) {
                int row = wm * 32 + mt * 16 + (lane & 15);
                int koff = ks * 16 + ((lane >> 4) << 3);
                ldsm_x4(af[mt][0], af[mt][1], af[mt][2], af[mt][3],
                        sbase + HOFF + row * 144 + koff * 2);
            }
            uint32_t bf2[2][4];
            #pragma unroll
            for (int nt2 = 0; nt2 < 2; nt2++) {
                int row = wn * 32 + nt2 * 16 + (((lane >> 4) & 1) << 3) + (lane & 7);
                int koff = ks * 16 + (((lane >> 3) & 1) << 3);
                ldsm_x4(bf2[nt2][0], bf2[nt2][1], bf2[nt2][2], bf2[nt2][3],
                        w2b + row * 144 + koff * 2);
            }
            #pragma unroll
            for (int mt = 0; mt < 2; mt++)
                #pragma unroll
                for (int nt = 0; nt < 4; nt++)
                    mma_bf16(acc2[mt][nt], af[mt],
                             bf2[nt >> 1][(nt & 1) * 2], bf2[nt >> 1][(nt & 1) * 2 + 1]);
        }
        __syncthreads();
    }

    #pragma unroll
    for (int mt = 0; mt < 2; mt++) {
        int r0 = mBase + wm * 32 + mt * 16 + lr;
        #pragma unroll
        for (int nt = 0; nt < 4; nt++) {
            int col = wn * 32 + nt * 8 + lc;
            float2 bb = *(const float2*)(b2 + col);
            float2 ra = *(const float2*)(res + (size_t)r0 * 128 + col);
            float2 rb = *(const float2*)(res + (size_t)(r0 + 8) * 128 + col);
            *(float2*)(out + (size_t)r0 * 128 + col) =
                make_float2(acc2[mt][nt][0] + bb.x + ra.x,
                            acc2[mt][nt][1] + bb.y + ra.y);
            *(float2*)(out + (size_t)(r0 + 8) * 128 + col) =
                make_float2(acc2[mt][nt][2] + bb.x + rb.x,
                            acc2[mt][nt][3] + bb.y + rb.y);
        }
    }
}

// ---------------------------------------------------------------------------
// Flash-style HMMA window attention + fused LEPE, templated on branch (R12).
// One block per (branch, window, head): 3584 blocks, 224 threads (7 warps).
// ---------------------------------------------------------------------------
#define AROW 80   // bytes per smem row in attention tiles (40 bf16)

template<int BRANCH>
__device__ __forceinline__ void attn_body(
    const __nv_bfloat16* __restrict__ qkv,
    const float* __restrict__ cw0, const float* __restrict__ cb0,
    const float* __restrict__ cw1, const float* __restrict__ cb1,
    __nv_bfloat16* __restrict__ outp,
    char* smQc, char* smKc, char* smVc, float* cwS, float* cbS,
    int rem)
{
    constexpr int Hsp = BRANCH ? 2 : RESO_;
    constexpr int Wsp = BRANCH ? RESO_ : 2;

    int win = rem >> 1;
    int head = rem & 1;
    int b = win / NWIN_;
    int slot = win - b * NWIN_;
    int cb = BRANCH * 64 + head * 32;
    int tid = threadIdx.x;
    int warp = tid >> 5;
    int lane = tid & 31;
    const float kscale = 0.17677669529663687f * 1.4426950408889634f;

    uint32_t sQ = smem_u32(smQc);
    uint32_t sK = smem_u32(smKc);
    uint32_t sV = smem_u32(smVc);

    {
        const float* cw = (BRANCH ? cw1 : cw0) + head * 32 * 9;
        const float* cbp = (BRANCH ? cb1 : cb0) + head * 32;
        for (int i = tid; i < 288; i += 224) {
            int d = i / 9, wi = i - d * 9;
            cwS[wi * 32 + d] = cw[i];
        }
        if (tid < 32) cbS[tid] = cbp[tid];
    }

    #pragma unroll
    for (int tile = 0; tile < 3; tile++) {
        char* dst = (tile == 0 ? smQc : tile == 1 ? smKc : smVc);
        #pragma unroll
        for (int it = 0; it < 2; it++) {
            int idx = it * 224 + tid;
            int t = idx >> 2;
            int f = idx & 3;
            int pix;
            if (BRANCH == 0) {
                pix = (t >> 1) * RESO_ + slot * 2 + (t & 1);
            } else {
                int hs = (t >= RESO_) ? 1 : 0;
                pix = (slot * 2 + hs) * RESO_ + (t - hs * RESO_);
            }
            size_t ro = ((size_t)(b * L_ + pix)) * 384 + cb + tile * 128 + f * 8;
            *(uint4*)(dst + t * AROW + f * 16) = *(const uint4*)(qkv + ro);
        }
    }
    __syncthreads();

    uint32_t af[2][4];
    #pragma unroll
    for (int kt = 0; kt < 2; kt++) {
        int row = warp * 16 + (lane & 15);
        int koff = kt * 16 + ((lane >> 4) << 3);
        ldsm_x4(af[kt][0], af[kt][1], af[kt][2], af[kt][3],
                sQ + row * AROW + koff * 2);
    }

    float s[14][4];
    #pragma unroll
    for (int nt = 0; nt < 14; nt++) {
        s[nt][0] = s[nt][1] = s[nt][2] = s[nt][3] = 0.0f;
        uint32_t kb[4];
        ldsm_x4(kb[0], kb[1], kb[2], kb[3],
                sK + (nt * 8 + (lane & 7)) * AROW + (lane >> 3) * 16);
        mma_bf16(s[nt], af[0], kb[0], kb[1]);
        mma_bf16(s[nt], af[1], kb[2], kb[3]);
    }

    float m0 = -1e30f, m1 = -1e30f;
    #pragma unroll
    for (int nt = 0; nt < 14; nt++) {
        m0 = fmaxf(m0, fmaxf(s[nt][0], s[nt][1]));
        m1 = fmaxf(m1, fmaxf(s[nt][2], s[nt][3]));
    }
    #pragma unroll
    for (int o = 1; o <= 2; o <<= 1) {
        m0 = fmaxf(m0, __shfl_xor_sync(0xffffffffu, m0, o));
        m1 = fmaxf(m1, __shfl_xor_sync(0xffffffffu, m1, o));
    }
    float m0k = m0 * kscale;
    float m1k = m1 * kscale;
    float sum0 = 0.0f, sum1 = 0.0f;
    uint32_t p01[14], p23[14];
    #pragma unroll
    for (int nt = 0; nt < 14; nt++) {
        float e0 = exp2f(fmaf(s[nt][0], kscale, -m0k));
        float e1 = exp2f(fmaf(s[nt][1], kscale, -m0k));
        float e2 = exp2f(fmaf(s[nt][2], kscale, -m1k));
        float e3 = exp2f(fmaf(s[nt][3], kscale, -m1k));
        sum0 += e0 + e1;
        sum1 += e2 + e3;
        __nv_bfloat162 pa = __floats2bfloat162_rn(e0, e1);
        __nv_bfloat162 pb = __floats2bfloat162_rn(e2, e3);
        p01[nt] = *reinterpret_cast<uint32_t*>(&pa);
        p23[nt] = *reinterpret_cast<uint32_t*>(&pb);
    }
    #pragma unroll
    for (int o = 1; o <= 2; o <<= 1) {
        sum0 += __shfl_xor_sync(0xffffffffu, sum0, o);
        sum1 += __shfl_xor_sync(0xffffffffu, sum1, o);
    }
    float inv0 = 1.0f / sum0;
    float inv1 = 1.0f / sum1;

    float oacc[4][4];
    #pragma unroll
    for (int nt = 0; nt < 4; nt++)
        oacc[nt][0] = oacc[nt][1] = oacc[nt][2] = oacc[nt][3] = 0.0f;

    #pragma unroll
    for (int kt = 0; kt < 7; kt++) {
        uint32_t pa[4] = {p01[2 * kt], p23[2 * kt], p01[2 * kt + 1], p23[2 * kt + 1]};
        uint32_t vb[4], vb2[4];
        uint32_t vaddr = sV + (kt * 16 + (lane & 15)) * AROW + (lane >> 4) * 16;
        ldsm_x4_t(vb[0],  vb[1],  vb[2],  vb[3],  vaddr);
        ldsm_x4_t(vb2[0], vb2[1], vb2[2], vb2[3], vaddr + 32);
        mma_bf16(oacc[0], pa, vb[0],  vb[1]);
        mma_bf16(oacc[1], pa, vb[2],  vb[3]);
        mma_bf16(oacc[2], pa, vb2[0], vb2[1]);
        mma_bf16(oacc[3], pa, vb2[2], vb2[3]);
    }

    const __nv_bfloat16* Vbf = (const __nv_bfloat16*)smVc;
    int lr = lane >> 2;
    int lc = (lane & 3) * 2;

    #pragma unroll
    for (int half = 0; half < 2; half++) {
        int tok = warp * 16 + lr + half * 8;
        float inv = half ? inv1 : inv0;
        int hs, ws;
        if (BRANCH == 0) { hs = tok >> 1; ws = tok & 1; }
        else             { hs = (tok >= RESO_) ? 1 : 0; ws = tok - hs * RESO_; }

        float l[8];
        #pragma unroll
        for (int nt = 0; nt < 4; nt++) {
            l[nt * 2]     = cbS[nt * 8 + lc];
            l[nt * 2 + 1] = cbS[nt * 8 + lc + 1];
        }
        #pragma unroll
        for (int wi = 0; wi < 9; wi++) {
            int dy = wi / 3 - 1, dx = wi - (wi / 3) * 3 - 1;
            int y = hs + dy, x = ws + dx;
            if (y >= 0 && y < Hsp && x >= 0 && x < Wsp) {
                const __nv_bfloat16* vp = Vbf + (y * Wsp + x) * 40;
                const float* wp = cwS + wi * 32;
                #pragma unroll
                for (int nt = 0; nt < 4; nt++) {
                    int d0 = nt * 8 + lc;
                    float2 vv = __bfloat1622float2(*(const __nv_bfloat162*)(vp + d0));
                    l[nt * 2]     += wp[d0]     * vv.x;
                    l[nt * 2 + 1] += wp[d0 + 1] * vv.y;
                }
            }
        }

        int pix;
        if (BRANCH == 0) pix = hs * RESO_ + slot * 2 + ws;
        else             pix = (slot * 2 + hs) * RESO_ + ws;
        __nv_bfloat16* op = outp + ((size_t)(b * L_ + pix)) * C_ + cb;

        #pragma unroll
        for (int nt = 0; nt < 4; nt++) {
            float v0 = oacc[nt][half * 2]     * inv + l[nt * 2];
            float v1 = oacc[nt][half * 2 + 1] * inv + l[nt * 2 + 1];
            __nv_bfloat162 pr = __floats2bfloat162_rn(v0, v1);
            *(__nv_bfloat162*)(op + nt * 8 + lc) = pr;
        }
    }
}

__global__ __launch_bounds__(224, 4) void attn_kernel(
    const __nv_bfloat16* __restrict__ qkv,
    const float* __restrict__ cw0, const float* __restrict__ cb0,
    const float* __restrict__ cw1, const float* __restrict__ cb1,
    __nv_bfloat16* __restrict__ outp)
{
    __shared__ __align__(16) char smQ[TOK_ * AROW];
    __shared__ __align__(16) char smK[TOK_ * AROW];
    __shared__ __align__(16) char smV[TOK_ * AROW];
    __shared__ float cwS[288];
    __shared__ float cbS[32];

    int bid = blockIdx.x;
    if (bid < 1792)
        attn_body<0>(qkv, cw0, cb0, cw1, cb1, outp, smQ, smK, smV, cwS, cbS, bid);
    else
        attn_body<1>(qkv, cw0, cb0, cw1, cb1, outp, smQ, smK, smV, cwS, cbS, bid - 1792);
}

// ---------------------------------------------------------------------------
extern "C" void kernel_launch(void* const* d_in, const int* in_sizes, int n_in,
                              void* d_out, int out_size)
{
    const float* x       = (const float*)d_in[0];
    const float* n1g     = (const float*)d_in[1];
    const float* n1b     = (const float*)d_in[2];
    const float* qkv_w   = (const float*)d_in[3];
    const float* proj_w  = (const float*)d_in[4];
    const float* proj_b  = (const float*)d_in[5];
    const float* conv_w0 = (const float*)d_in[6];
    const float* conv_b0 = (const float*)d_in[7];
    const float* conv_w1 = (const float*)d_in[8];
    const float* conv_b1 = (const float*)d_in[9];
    const float* n2g     = (const float*)d_in[10];
    const float* n2b     = (const float*)d_in[11];
    const float* fc1_w   = (const float*)d_in[12];
    const float* fc1_b   = (const float*)d_in[13];
    const float* fc2_w   = (const float*)d_in[14];
    const float* fc2_b   = (const float*)d_in[15];
    float* out = (float*)d_out;

    __nv_bfloat16 *ln, *qkvb, *attn, *wts;
    float *xr;
    cudaGetSymbolAddress((void**)&ln,   g_ln);
    cudaGetSymbolAddress((void**)&qkvb, g_qkv);
    cudaGetSymbolAddress((void**)&attn, g_attn);
    cudaGetSymbolAddress((void**)&xr,   g_x);
    cudaGetSymbolAddress((void**)&wts,  g_w);

    __nv_bfloat16* w_qkv = wts;                 // [384,128]
    __nv_bfloat16* w_prj = wts + 49152;         // [128,128]
    __nv_bfloat16* w_fc1 = wts + 65536;         // [512,128]
    __nv_bfloat16* w_fc2 = wts + 131072;        // [128,512]

    cudaFuncSetAttribute(mlp_kernel,
                         cudaFuncAttributeMaxDynamicSharedMemorySize, MLP_SMEM);
    cudaFuncSetAttribute(qkv_gemm_kernel,
                         cudaFuncAttributeMaxDynamicSharedMemorySize, QKV_SMEM);

    // 1. LN1 -> bf16 (+ folded weight convert in first 768 blocks)
    ln_conv_kernel<<<M_ / 8, 256>>>(x, n1g, n1b, ln,
                                    qkv_w, proj_w, fc1_w, fc2_w, wts);
    // 2. QKV GEMM (full-prefetch, 4 syncs) -> bf16
    qkv_gemm_kernel<<<dim3(3, M_ / 128), 256, QKV_SMEM>>>(ln, w_qkv, qkvb);
    // 3. Flash-style HMMA window attention + LEPE -> bf16
    attn_kernel<<<3584, 224>>>(qkvb, conv_w0, conv_b0, conv_w1, conv_b1, attn);
    // 4. proj GEMM + bias + residual(x) -> fp32 xr, fused LN2 -> bf16 ln
    proj_ln_kernel<<<dim3(1, M_ / 64), 256>>>(attn, w_prj, xr,
                                              proj_b, x, n2g, n2b, ln);
    // 5. fused MLP (double-buffered): GELU(ln@W1+b1)@W2 + b2 + xr -> fp32 out
    mlp_kernel<<<dim3(1, M_ / 64), 256, MLP_SMEM>>>(ln, w_fc1, w_fc2, out,
                                                    fc1_b, fc2_b, xr);
}